// round 4
// baseline (speedup 1.0000x reference)
#include <cuda_runtime.h>

// ---------------------------------------------------------------------------
// GPT-style transformer forward, fp32 baseline.
// B=4, T=1024, D=1024, H=16, HS=64, L=8, FF=4096, V=8192
// ---------------------------------------------------------------------------

#define Dm   1024
#define FFm  4096
#define Vm   8192
#define Hm   16
#define HSm  64
#define Lm   8
#define Bm_  4
#define Tm   1024
#define Mrows (Bm_ * Tm)   // 4096

// Scratch (device globals; no allocations allowed)
__device__ float g_h  [Mrows * Dm];
__device__ float g_hn [Mrows * Dm];
__device__ float g_q  [Mrows * Dm];
__device__ float g_k  [Mrows * Dm];
__device__ float g_v  [Mrows * Dm];
__device__ float g_att[Mrows * Dm];
__device__ float g_wq [Dm * Dm];
__device__ float g_wk [Dm * Dm];
__device__ float g_wv [Dm * Dm];
__device__ float g_ffn[Mrows * FFm];

// ---------------------------------------------------------------------------
// Embedding: h[row] = tok_embd[x[row]] + pos_embd[x[row]]   (pos quirk!)
// ---------------------------------------------------------------------------
__global__ void k_embed(const int* __restrict__ x, const float* __restrict__ tok,
                        const float* __restrict__ pos, float* __restrict__ out)
{
    int row = blockIdx.x;
    int t = x[row];
    const float4* te = (const float4*)(tok + (size_t)t * Dm);
    const float4* pe = (const float4*)(pos + (size_t)t * Dm);
    float4* o = (float4*)(out + (size_t)row * Dm);
    int i = threadIdx.x;                 // 256 threads == 256 float4 per row
    float4 a = te[i], b = pe[i];
    o[i] = make_float4(a.x + b.x, a.y + b.y, a.z + b.z, a.w + b.w);
}

// ---------------------------------------------------------------------------
// LayerNorm over D=1024, one block (256 thr) per row, 4 elems/thread.
// ---------------------------------------------------------------------------
__global__ void k_ln(const float* __restrict__ in, const float* __restrict__ gw,
                     const float* __restrict__ bw, float* __restrict__ out)
{
    __shared__ float red[8];
    int row = blockIdx.x;
    int c = threadIdx.x * 4;
    const float* xr = in + (size_t)row * Dm;
    float4 xv = *(const float4*)(xr + c);
    float s = xv.x + xv.y + xv.z + xv.w;
    #pragma unroll
    for (int o = 16; o; o >>= 1) s += __shfl_xor_sync(0xffffffffu, s, o);
    int wid = threadIdx.x >> 5, lid = threadIdx.x & 31;
    if (lid == 0) red[wid] = s;
    __syncthreads();
    float tot = 0.f;
    #pragma unroll
    for (int i = 0; i < 8; i++) tot += red[i];
    float mean = tot * (1.0f / Dm);
    float d0 = xv.x - mean, d1 = xv.y - mean, d2 = xv.z - mean, d3 = xv.w - mean;
    float s2 = d0*d0 + d1*d1 + d2*d2 + d3*d3;
    __syncthreads();
    #pragma unroll
    for (int o = 16; o; o >>= 1) s2 += __shfl_xor_sync(0xffffffffu, s2, o);
    if (lid == 0) red[wid] = s2;
    __syncthreads();
    float v2 = 0.f;
    #pragma unroll
    for (int i = 0; i < 8; i++) v2 += red[i];
    float rstd = rsqrtf(v2 * (1.0f / Dm) + 1e-5f);
    float4 gv = *(const float4*)(gw + c);
    float4 bv = *(const float4*)(bw + c);
    float4 ov = make_float4(d0 * rstd * gv.x + bv.x, d1 * rstd * gv.y + bv.y,
                            d2 * rstd * gv.z + bv.z, d3 * rstd * gv.w + bv.w);
    *(float4*)(out + (size_t)row * Dm + c) = ov;
}

// ---------------------------------------------------------------------------
// Repack wq/wk/wv[l] from (H, D, HS) to row-major (D, H*HS)
// ---------------------------------------------------------------------------
__global__ void k_repack(const float* __restrict__ wq, const float* __restrict__ wk,
                         const float* __restrict__ wv, float* __restrict__ oq,
                         float* __restrict__ ok, float* __restrict__ ov)
{
    int idx = blockIdx.x * 256 + threadIdx.x;       // 0 .. D*D-1
    int d = idx >> 10, n = idx & 1023;
    int src = ((n >> 6) << 16) + (d << 6) + (n & 63);  // h*D*HS + d*HS + e
    oq[idx] = wq[src];
    ok[idx] = wk[src];
    ov[idx] = wv[src];
}

// ---------------------------------------------------------------------------
// SGEMM: C[M,N] = A[M,K] * B[K,N] (+ bias[N]) (relu?) (+ res[M,N])
// 128x128 tile, K-step 16, 256 threads, 8x8 microtile.
// ---------------------------------------------------------------------------
__global__ __launch_bounds__(256, 2)
void k_gemm(const float* __restrict__ A, const float* __restrict__ Bmat,
            const float* __restrict__ bias, const float* __restrict__ res,
            float* __restrict__ C, int M, int N, int K, int relu)
{
    __shared__ __align__(16) float As[16][132];   // [k][m], padded
    __shared__ __align__(16) float Bs[16][128];   // [k][n]
    int tid = threadIdx.x;
    int tx = tid & 15, ty = tid >> 4;
    int m0 = blockIdx.y << 7, n0 = blockIdx.x << 7;

    float acc[8][8];
    #pragma unroll
    for (int i = 0; i < 8; i++)
        #pragma unroll
        for (int j = 0; j < 8; j++) acc[i][j] = 0.f;

    for (int k0 = 0; k0 < K; k0 += 16) {
        #pragma unroll
        for (int i = 0; i < 2; i++) {
            int lin = tid + (i << 8);
            int ar = lin >> 2, ac = (lin & 3) << 2;
            float4 av = *(const float4*)(A + (size_t)(m0 + ar) * K + k0 + ac);
            As[ac + 0][ar] = av.x;
            As[ac + 1][ar] = av.y;
            As[ac + 2][ar] = av.z;
            As[ac + 3][ar] = av.w;
            int br = lin >> 5, bc = (lin & 31) << 2;
            *(float4*)&Bs[br][bc] =
                *(const float4*)(Bmat + (size_t)(k0 + br) * N + n0 + bc);
        }
        __syncthreads();
        #pragma unroll
        for (int kk = 0; kk < 16; kk++) {
            float4 a0 = *(const float4*)&As[kk][ty << 3];
            float4 a1 = *(const float4*)&As[kk][(ty << 3) + 4];
            float4 b0 = *(const float4*)&Bs[kk][tx << 3];
            float4 b1 = *(const float4*)&Bs[kk][(tx << 3) + 4];
            float av[8] = {a0.x, a0.y, a0.z, a0.w, a1.x, a1.y, a1.z, a1.w};
            float bv[8] = {b0.x, b0.y, b0.z, b0.w, b1.x, b1.y, b1.z, b1.w};
            #pragma unroll
            for (int i = 0; i < 8; i++)
                #pragma unroll
                for (int j = 0; j < 8; j++)
                    acc[i][j] += av[i] * bv[j];
        }
        __syncthreads();
    }

    #pragma unroll
    for (int i = 0; i < 8; i++) {
        int r = m0 + (ty << 3) + i;
        size_t off = (size_t)r * N + n0 + (tx << 3);
        #pragma unroll
        for (int jj = 0; jj < 8; jj += 4) {
            float4 cv = make_float4(acc[i][jj], acc[i][jj + 1],
                                    acc[i][jj + 2], acc[i][jj + 3]);
            if (bias) {
                float4 bb = *(const float4*)(bias + n0 + (tx << 3) + jj);
                cv.x += bb.x; cv.y += bb.y; cv.z += bb.z; cv.w += bb.w;
            }
            if (relu) {
                cv.x = fmaxf(cv.x, 0.f); cv.y = fmaxf(cv.y, 0.f);
                cv.z = fmaxf(cv.z, 0.f); cv.w = fmaxf(cv.w, 0.f);
            }
            if (res) {
                float4 rr = *(const float4*)(res + off + jj);
                cv.x += rr.x; cv.y += rr.y; cv.z += rr.z; cv.w += rr.w;
            }
            *(float4*)(C + off + jj) = cv;
        }
    }
}

// ---------------------------------------------------------------------------
// Causal attention, flash-style. Block = (b, h, 64-query tile), 256 threads.
// q/k/v layout: row = b*T + t, col = h*64 + e (i.e. [M, 1024]).
// ---------------------------------------------------------------------------
#define ATT_SMEM ((4 * 64 * 68 + 192) * 4)

__global__ __launch_bounds__(256)
void k_attn(const float* __restrict__ Q, const float* __restrict__ Kx,
            const float* __restrict__ Vx, float* __restrict__ O)
{
    extern __shared__ __align__(16) float sm[];
    float* QsT  = sm;                  // [e][r] 64x68 (scaled)
    float* KsT  = sm + 64 * 68;       // [e][j]
    float* Vs   = sm + 2 * 64 * 68;   // [j][e]
    float* Ss   = sm + 3 * 64 * 68;   // [q][j]
    float* mRow = sm + 4 * 64 * 68;
    float* sRow = mRow + 64;
    float* fRow = sRow + 64;

    int qt = blockIdx.x;              // 0..15
    int bh = blockIdx.y;              // 0..63
    int b = bh >> 4, h = bh & 15;
    int tid = threadIdx.x;
    int tx = tid & 15, ty = tid >> 4;
    size_t base = ((size_t)b * Tm) * Dm + h * HSm;

    // Load Q tile (transposed + pre-scaled by 1/sqrt(HS) = 0.125)
    for (int i = tid; i < 1024; i += 256) {
        int r = i >> 4, c = (i & 15) << 2;
        float4 qv = *(const float4*)(Q + base + (size_t)(qt * 64 + r) * Dm + c);
        QsT[(c + 0) * 68 + r] = qv.x * 0.125f;
        QsT[(c + 1) * 68 + r] = qv.y * 0.125f;
        QsT[(c + 2) * 68 + r] = qv.z * 0.125f;
        QsT[(c + 3) * 68 + r] = qv.w * 0.125f;
    }
    if (tid < 64) { mRow[tid] = -1e30f; sRow[tid] = 0.f; }

    float acc[4][4] = {};

    for (int kt = 0; kt <= qt; kt++) {
        __syncthreads();   // previous PV done / Q+state visible (first iter)
        for (int i = tid; i < 1024; i += 256) {
            int r = i >> 4, c = (i & 15) << 2;
            float4 kv = *(const float4*)(Kx + base + (size_t)(kt * 64 + r) * Dm + c);
            KsT[(c + 0) * 68 + r] = kv.x;
            KsT[(c + 1) * 68 + r] = kv.y;
            KsT[(c + 2) * 68 + r] = kv.z;
            KsT[(c + 3) * 68 + r] = kv.w;
            float4 vv = *(const float4*)(Vx + base + (size_t)(kt * 64 + r) * Dm + c);
            *(float4*)&Vs[r * 68 + c] = vv;
        }
        __syncthreads();

        // S = Q K^T  (each thread: 4 q-rows x 4 k-cols)
        float sc[4][4] = {};
        #pragma unroll 8
        for (int e = 0; e < 64; e++) {
            float4 qv = *(const float4*)&QsT[e * 68 + (ty << 2)];
            float4 kv = *(const float4*)&KsT[e * 68 + (tx << 2)];
            sc[0][0] += qv.x * kv.x; sc[0][1] += qv.x * kv.y;
            sc[0][2] += qv.x * kv.z; sc[0][3] += qv.x * kv.w;
            sc[1][0] += qv.y * kv.x; sc[1][1] += qv.y * kv.y;
            sc[1][2] += qv.y * kv.z; sc[1][3] += qv.y * kv.w;
            sc[2][0] += qv.z * kv.x; sc[2][1] += qv.z * kv.y;
            sc[2][2] += qv.z * kv.z; sc[2][3] += qv.z * kv.w;
            sc[3][0] += qv.w * kv.x; sc[3][1] += qv.w * kv.y;
            sc[3][2] += qv.w * kv.z; sc[3][3] += qv.w * kv.w;
        }
        #pragma unroll
        for (int i = 0; i < 4; i++)
            *(float4*)&Ss[((ty << 2) + i) * 68 + (tx << 2)] =
                make_float4(sc[i][0], sc[i][1], sc[i][2], sc[i][3]);
        __syncthreads();

        // Online softmax update: one thread per query row
        if (tid < 64) {
            int r = tid;
            int lim = (kt == qt) ? r : 63;        // causal mask on diag tile
            float mOld = mRow[r];
            float mx = mOld;
            for (int j = 0; j <= lim; j++) mx = fmaxf(mx, Ss[r * 68 + j]);
            float f = __expf(mOld - mx);
            float sum = sRow[r] * f;
            for (int j = 0; j < 64; j++) {
                float p = (j <= lim) ? __expf(Ss[r * 68 + j] - mx) : 0.f;
                Ss[r * 68 + j] = p;
                sum += p;
            }
            mRow[r] = mx; sRow[r] = sum; fRow[r] = f;
        }
        __syncthreads();

        // Rescale accumulators, then O += P V
        float f0 = fRow[(ty << 2) + 0], f1 = fRow[(ty << 2) + 1];
        float f2 = fRow[(ty << 2) + 2], f3 = fRow[(ty << 2) + 3];
        #pragma unroll
        for (int j = 0; j < 4; j++) {
            acc[0][j] *= f0; acc[1][j] *= f1; acc[2][j] *= f2; acc[3][j] *= f3;
        }
        #pragma unroll 8
        for (int j = 0; j < 64; j++) {
            float4 vv = *(const float4*)&Vs[j * 68 + (tx << 2)];
            float p0 = Ss[((ty << 2) + 0) * 68 + j];
            float p1 = Ss[((ty << 2) + 1) * 68 + j];
            float p2 = Ss[((ty << 2) + 2) * 68 + j];
            float p3 = Ss[((ty << 2) + 3) * 68 + j];
            acc[0][0] += p0 * vv.x; acc[0][1] += p0 * vv.y;
            acc[0][2] += p0 * vv.z; acc[0][3] += p0 * vv.w;
            acc[1][0] += p1 * vv.x; acc[1][1] += p1 * vv.y;
            acc[1][2] += p1 * vv.z; acc[1][3] += p1 * vv.w;
            acc[2][0] += p2 * vv.x; acc[2][1] += p2 * vv.y;
            acc[2][2] += p2 * vv.z; acc[2][3] += p2 * vv.w;
            acc[3][0] += p3 * vv.x; acc[3][1] += p3 * vv.y;
            acc[3][2] += p3 * vv.z; acc[3][3] += p3 * vv.w;
        }
    }

    #pragma unroll
    for (int i = 0; i < 4; i++) {
        float inv = 1.0f / sRow[(ty << 2) + i];
        size_t off = base + (size_t)(qt * 64 + (ty << 2) + i) * Dm + (tx << 2);
        *(float4*)(O + off) = make_float4(acc[i][0] * inv, acc[i][1] * inv,
                                          acc[i][2] * inv, acc[i][3] * inv);
    }
}

// ---------------------------------------------------------------------------
// Host orchestration (graph-capturable: kernel launches only)
// ---------------------------------------------------------------------------
extern "C" void kernel_launch(void* const* d_in, const int* in_sizes, int n_in,
                              void* d_out, int out_size)
{
    (void)in_sizes; (void)n_in; (void)out_size;
    const int*   x      = (const int*)  d_in[0];
    const float* tok    = (const float*)d_in[1];
    const float* pos    = (const float*)d_in[2];
    const float* wq     = (const float*)d_in[3];
    const float* wk     = (const float*)d_in[4];
    const float* wv     = (const float*)d_in[5];
    const float* w_o    = (const float*)d_in[6];
    const float* b_o    = (const float*)d_in[7];
    const float* ln1_g  = (const float*)d_in[8];
    const float* ln1_b  = (const float*)d_in[9];
    const float* ln2_g  = (const float*)d_in[10];
    const float* ln2_b  = (const float*)d_in[11];
    const float* w1     = (const float*)d_in[12];
    const float* b1     = (const float*)d_in[13];
    const float* w2     = (const float*)d_in[14];
    const float* b2     = (const float*)d_in[15];
    const float* lnf_g  = (const float*)d_in[16];
    const float* lnf_b  = (const float*)d_in[17];
    const float* w_lm   = (const float*)d_in[18];
    const float* b_lm   = (const float*)d_in[19];
    float* out = (float*)d_out;

    float *hb, *hn, *qb, *kb, *vb, *ab, *wqr, *wkr, *wvr, *ff;
    cudaGetSymbolAddress((void**)&hb,  g_h);
    cudaGetSymbolAddress((void**)&hn,  g_hn);
    cudaGetSymbolAddress((void**)&qb,  g_q);
    cudaGetSymbolAddress((void**)&kb,  g_k);
    cudaGetSymbolAddress((void**)&vb,  g_v);
    cudaGetSymbolAddress((void**)&ab,  g_att);
    cudaGetSymbolAddress((void**)&wqr, g_wq);
    cudaGetSymbolAddress((void**)&wkr, g_wk);
    cudaGetSymbolAddress((void**)&wvr, g_wv);
    cudaGetSymbolAddress((void**)&ff,  g_ffn);

    cudaFuncSetAttribute(k_attn, cudaFuncAttributeMaxDynamicSharedMemorySize,
                         ATT_SMEM);

    dim3 g1(Dm / 128, Mrows / 128);   // N=1024
    dim3 g2(FFm / 128, Mrows / 128);  // N=4096
    dim3 gl(Vm / 128, Mrows / 128);   // N=8192
    dim3 ga(Tm / 64, Bm_ * Hm);       // attention grid

    k_embed<<<Mrows, 256>>>(x, tok, pos, hb);

    for (int l = 0; l < Lm; l++) {
        size_t wofs = (size_t)l * Hm * Dm * HSm;
        k_ln<<<Mrows, 256>>>(hb, ln1_g + l * Dm, ln1_b + l * Dm, hn);
        k_repack<<<Dm * Dm / 256, 256>>>(wq + wofs, wk + wofs, wv + wofs,
                                         wqr, wkr, wvr);
        k_gemm<<<g1, 256>>>(hn, wqr, nullptr, nullptr, qb, Mrows, Dm, Dm, 0);
        k_gemm<<<g1, 256>>>(hn, wkr, nullptr, nullptr, kb, Mrows, Dm, Dm, 0);
        k_gemm<<<g1, 256>>>(hn, wvr, nullptr, nullptr, vb, Mrows, Dm, Dm, 0);
        k_attn<<<ga, 256, ATT_SMEM>>>(qb, kb, vb, ab);
        // h = hn + att @ w_o + b_o   (residual is hn per reference)
        k_gemm<<<g1, 256>>>(ab, w_o + (size_t)l * Dm * Dm, b_o + l * Dm, hn,
                            hb, Mrows, Dm, Dm, 0);
        k_ln<<<Mrows, 256>>>(hb, ln2_g + l * Dm, ln2_b + l * Dm, hn);
        // ffn1 = relu(hn @ w1 + b1)
        k_gemm<<<g2, 256>>>(hn, w1 + (size_t)l * Dm * FFm, b1 + l * FFm,
                            nullptr, ff, Mrows, FFm, Dm, 1);
        // h = hn + ffn1 @ w2 + b2    (residual is hn2 = hn)
        k_gemm<<<g1, 256>>>(ff, w2 + (size_t)l * FFm * Dm, b2 + l * Dm, hn,
                            hb, Mrows, Dm, FFm, 0);
    }

    k_ln<<<Mrows, 256>>>(hb, lnf_g, lnf_b, hn);
    k_gemm<<<gl, 256>>>(hn, w_lm, b_lm, nullptr, out, Mrows, Vm, Dm, 0);
}

// round 6
// speedup vs baseline: 2.0008x; 2.0008x over previous
#include <cuda_runtime.h>
#include <cuda_bf16.h>
#include <cstdint>

// ---------------------------------------------------------------------------
// GPT-style transformer forward. GEMMs on tensor cores via mma.sync (bf16x3
// split for fp32-like accuracy); attention fp32 flash-style SIMT.
// B=4, T=1024, D=1024, H=16, HS=64, L=8, FF=4096, V=8192
// ---------------------------------------------------------------------------

#define Dm   1024
#define FFm  4096
#define Vm   8192
#define Hm   16
#define HSm  64
#define Lm   8
#define Bm_  4
#define Tm   1024
#define Mrows (Bm_ * Tm)   // 4096

// fp32 activation scratch
__device__ float g_h  [Mrows * Dm];
__device__ float g_hn [Mrows * Dm];
__device__ float g_q  [Mrows * Dm];
__device__ float g_k  [Mrows * Dm];
__device__ float g_v  [Mrows * Dm];
__device__ float g_att[Mrows * Dm];
__device__ float g_ffn[Mrows * FFm];

// bf16 split activation scratch (A operand, [M][K] row-major)
__device__ __nv_bfloat16 g_ah[Mrows * FFm];
__device__ __nv_bfloat16 g_al[Mrows * FFm];

// bf16 split weight scratch ([N][K] transposed layout), reused per layer
__device__ __nv_bfloat16 g_qh[Dm * Dm],  g_ql[Dm * Dm];
__device__ __nv_bfloat16 g_kh[Dm * Dm],  g_kl[Dm * Dm];
__device__ __nv_bfloat16 g_vh[Dm * Dm],  g_vl[Dm * Dm];
__device__ __nv_bfloat16 g_oh[Dm * Dm],  g_ol[Dm * Dm];
__device__ __nv_bfloat16 g_1h[Dm * FFm], g_1l[Dm * FFm];
__device__ __nv_bfloat16 g_2h[Dm * FFm], g_2l[Dm * FFm];
__device__ __nv_bfloat16 g_lh[Dm * Vm],  g_ll[Dm * Vm];

// ---------------------------------------------------------------------------
// helpers
// ---------------------------------------------------------------------------
__device__ __forceinline__ uint32_t smem_u32(const void* p) {
    uint32_t a;
    asm("{ .reg .u64 t; cvta.to.shared.u64 t, %1; cvt.u32.u64 %0, t; }"
        : "=r"(a) : "l"(p));
    return a;
}

__device__ __forceinline__ void split_bf16(float f, __nv_bfloat16& h, __nv_bfloat16& l) {
    h = __float2bfloat16(f);
    l = __float2bfloat16(f - __bfloat162float(h));
}

__device__ __forceinline__ void ldsm4(uint32_t* r, uint32_t addr) {
    asm volatile("ldmatrix.sync.aligned.m8n8.x4.shared.b16 {%0,%1,%2,%3}, [%4];\n"
                 : "=r"(r[0]), "=r"(r[1]), "=r"(r[2]), "=r"(r[3]) : "r"(addr));
}

__device__ __forceinline__ void mma16816(float* c, const uint32_t* a, const uint32_t* b) {
    asm volatile(
        "mma.sync.aligned.m16n8k16.row.col.f32.bf16.bf16.f32 "
        "{%0,%1,%2,%3}, {%4,%5,%6,%7}, {%8,%9}, {%0,%1,%2,%3};\n"
        : "+f"(c[0]), "+f"(c[1]), "+f"(c[2]), "+f"(c[3])
        : "r"(a[0]), "r"(a[1]), "r"(a[2]), "r"(a[3]), "r"(b[0]), "r"(b[1]));
}

// ---------------------------------------------------------------------------
// Embedding: h[row] = tok_embd[x[row]] + pos_embd[x[row]]   (pos quirk!)
// ---------------------------------------------------------------------------
__global__ void k_embed(const int* __restrict__ x, const float* __restrict__ tok,
                        const float* __restrict__ pos, float* __restrict__ out)
{
    int row = blockIdx.x;
    int t = x[row];
    const float4* te = (const float4*)(tok + (size_t)t * Dm);
    const float4* pe = (const float4*)(pos + (size_t)t * Dm);
    float4* o = (float4*)(out + (size_t)row * Dm);
    int i = threadIdx.x;
    float4 a = te[i], b = pe[i];
    o[i] = make_float4(a.x + b.x, a.y + b.y, a.z + b.z, a.w + b.w);
}

// ---------------------------------------------------------------------------
// LayerNorm over D=1024, one block (256 thr) per row.
// ---------------------------------------------------------------------------
__global__ void k_ln(const float* __restrict__ in, const float* __restrict__ gw,
                     const float* __restrict__ bw, float* __restrict__ out)
{
    __shared__ float red[8];
    int row = blockIdx.x;
    int c = threadIdx.x * 4;
    const float* xr = in + (size_t)row * Dm;
    float4 xv = *(const float4*)(xr + c);
    float s = xv.x + xv.y + xv.z + xv.w;
    #pragma unroll
    for (int o = 16; o; o >>= 1) s += __shfl_xor_sync(0xffffffffu, s, o);
    int wid = threadIdx.x >> 5, lid = threadIdx.x & 31;
    if (lid == 0) red[wid] = s;
    __syncthreads();
    float tot = 0.f;
    #pragma unroll
    for (int i = 0; i < 8; i++) tot += red[i];
    float mean = tot * (1.0f / Dm);
    float d0 = xv.x - mean, d1 = xv.y - mean, d2 = xv.z - mean, d3 = xv.w - mean;
    float s2 = d0*d0 + d1*d1 + d2*d2 + d3*d3;
    __syncthreads();
    #pragma unroll
    for (int o = 16; o; o >>= 1) s2 += __shfl_xor_sync(0xffffffffu, s2, o);
    if (lid == 0) red[wid] = s2;
    __syncthreads();
    float v2 = 0.f;
    #pragma unroll
    for (int i = 0; i < 8; i++) v2 += red[i];
    float rstd = rsqrtf(v2 * (1.0f / Dm) + 1e-5f);
    float4 gv = *(const float4*)(gw + c);
    float4 bv = *(const float4*)(bw + c);
    float4 ov = make_float4(d0 * rstd * gv.x + bv.x, d1 * rstd * gv.y + bv.y,
                            d2 * rstd * gv.z + bv.z, d3 * rstd * gv.w + bv.w);
    *(float4*)(out + (size_t)row * Dm + c) = ov;
}

// ---------------------------------------------------------------------------
// Activation convert: fp32 [M,K] -> bf16 hi/lo [M,K] (elementwise)
// ---------------------------------------------------------------------------
__global__ void k_conv_a(const float* __restrict__ in,
                         __nv_bfloat16* __restrict__ oh,
                         __nv_bfloat16* __restrict__ ol)
{
    int idx = blockIdx.x * 256 + threadIdx.x;   // one float4 per thread
    float4 v = ((const float4*)in)[idx];
    __nv_bfloat16 h0, l0, h1, l1, h2, l2, h3, l3;
    split_bf16(v.x, h0, l0); split_bf16(v.y, h1, l1);
    split_bf16(v.z, h2, l2); split_bf16(v.w, h3, l3);
    __nv_bfloat162* oh2 = (__nv_bfloat162*)(oh + (size_t)idx * 4);
    __nv_bfloat162* ol2 = (__nv_bfloat162*)(ol + (size_t)idx * 4);
    oh2[0] = __halves2bfloat162(h0, h1); oh2[1] = __halves2bfloat162(h2, h3);
    ol2[0] = __halves2bfloat162(l0, l1); ol2[1] = __halves2bfloat162(l2, l3);
}

// ---------------------------------------------------------------------------
// Weight convert: qkv (H,D,HS) -> [N=H*HS][K=D] bf16 hi/lo
// ---------------------------------------------------------------------------
__global__ void k_conv_qkv(const float* __restrict__ wq, const float* __restrict__ wk,
                           const float* __restrict__ wv,
                           __nv_bfloat16* qh, __nv_bfloat16* ql,
                           __nv_bfloat16* kh, __nv_bfloat16* kl,
                           __nv_bfloat16* vh, __nv_bfloat16* vl)
{
    __shared__ float t[64][65];
    int h = blockIdx.y;
    int d0 = blockIdx.x << 6;
    int m = blockIdx.z;
    const float* src = (m == 0) ? wq : (m == 1) ? wk : wv;
    __nv_bfloat16* oh = (m == 0) ? qh : (m == 1) ? kh : vh;
    __nv_bfloat16* ol = (m == 0) ? ql : (m == 1) ? kl : vl;

    const float* base = src + ((size_t)h << 16) + ((size_t)d0 << 6);
    for (int i = threadIdx.x; i < 1024; i += 256) {
        int di = i >> 4, e4 = (i & 15) << 2;
        float4 v = *(const float4*)(base + ((size_t)di << 6) + e4);
        t[di][e4] = v.x; t[di][e4+1] = v.y; t[di][e4+2] = v.z; t[di][e4+3] = v.w;
    }
    __syncthreads();
    for (int i = threadIdx.x; i < 2048; i += 256) {
        int e = i >> 5, d2 = (i & 31) << 1;
        __nv_bfloat16 h0, l0, h1, l1;
        split_bf16(t[d2][e], h0, l0);
        split_bf16(t[d2 + 1][e], h1, l1);
        size_t off = ((size_t)(h * 64 + e) << 10) + d0 + d2;
        *(__nv_bfloat162*)(oh + off) = __halves2bfloat162(h0, h1);
        *(__nv_bfloat162*)(ol + off) = __halves2bfloat162(l0, l1);
    }
}

// ---------------------------------------------------------------------------
// Weight convert (transpose): in [Kd,Nd] fp32 -> out [Nd][Kd] bf16 hi/lo
// ---------------------------------------------------------------------------
__global__ void k_conv_t(const float* __restrict__ in,
                         __nv_bfloat16* __restrict__ oh,
                         __nv_bfloat16* __restrict__ ol, int Kd, int Nd)
{
    __shared__ float t[64][65];
    int k0 = blockIdx.y << 6, n0 = blockIdx.x << 6;
    for (int i = threadIdx.x; i < 1024; i += 256) {
        int r = i >> 4, c4 = (i & 15) << 2;
        float4 v = *(const float4*)(in + (size_t)(k0 + r) * Nd + n0 + c4);
        t[r][c4] = v.x; t[r][c4+1] = v.y; t[r][c4+2] = v.z; t[r][c4+3] = v.w;
    }
    __syncthreads();
    for (int i = threadIdx.x; i < 2048; i += 256) {
        int n = i >> 5, k2 = (i & 31) << 1;
        __nv_bfloat16 h0, l0, h1, l1;
        split_bf16(t[k2][n], h0, l0);
        split_bf16(t[k2 + 1][n], h1, l1);
        size_t off = (size_t)(n0 + n) * Kd + k0 + k2;
        *(__nv_bfloat162*)(oh + off) = __halves2bfloat162(h0, h1);
        *(__nv_bfloat162*)(ol + off) = __halves2bfloat162(l0, l1);
    }
}

// ---------------------------------------------------------------------------
// Tensor-core GEMM (mma.sync, bf16x3):
// C[M,N] = A[M,K] * B^T  (A given as [M][K] hi/lo; B given as [N][K] hi/lo)
// 128x128 CTA tile, BK=32, 256 threads, double-buffered cp.async.
// Padded smem stride 40 bf16 (80B) -> conflict-free ldmatrix.
// ---------------------------------------------------------------------------
#define BK 32
#define SROW 40                       // bf16 elems per smem row
#define TILE_BYTES (128 * SROW * 2)   // 10240
#define STAGE_BYTES (4 * TILE_BYTES)  // 40960
#define GEMM_SMEM (2 * STAGE_BYTES)   // 81920

__device__ __forceinline__ void issue_stage(
    uint32_t sb, int stage,
    const __nv_bfloat16* Ah, const __nv_bfloat16* Al,
    const __nv_bfloat16* Bh, const __nv_bfloat16* Bl,
    int m0, int n0, int kc, int K, int tid)
{
    uint32_t sbase = sb + stage * STAGE_BYTES;
    #pragma unroll
    for (int i = 0; i < 8; i++) {
        int id = (i << 8) + tid;          // 0..2047
        int tile = id >> 9;               // 0..3 : AH AL BH BL
        int r = (id >> 2) & 127;
        int c = id & 3;                   // 16B chunk within 64B row data
        const __nv_bfloat16* src =
            (tile == 0) ? Ah : (tile == 1) ? Al : (tile == 2) ? Bh : Bl;
        int rowg = ((tile < 2) ? m0 : n0) + r;
        const void* g = src + (size_t)rowg * K + kc + (c << 3);
        uint32_t s = sbase + tile * TILE_BYTES + r * (SROW * 2) + (c << 4);
        asm volatile("cp.async.cg.shared.global [%0], [%1], 16;\n"
                     :: "r"(s), "l"(g));
    }
}

__global__ __launch_bounds__(256, 2)
void k_gemm_mma(const __nv_bfloat16* __restrict__ Ah, const __nv_bfloat16* __restrict__ Al,
                const __nv_bfloat16* __restrict__ Bh, const __nv_bfloat16* __restrict__ Bl,
                const float* __restrict__ bias, const float* __restrict__ res,
                float* __restrict__ C, int M, int N, int K, int relu)
{
    extern __shared__ __align__(128) char sm2[];
    uint32_t sb = smem_u32(sm2);
    int tid = threadIdx.x;
    int lane = tid & 31, wid = tid >> 5;
    int wm = (wid & 1) << 6;    // warp M offset (0/64)
    int wn = (wid >> 1) << 5;   // warp N offset (0/32/64/96)
    int m0 = blockIdx.y << 7, n0 = blockIdx.x << 7;

    float acc[4][4][4];
    #pragma unroll
    for (int i = 0; i < 4; i++)
        #pragma unroll
        for (int j = 0; j < 4; j++)
            #pragma unroll
            for (int k = 0; k < 4; k++) acc[i][j][k] = 0.f;

    issue_stage(sb, 0, Ah, Al, Bh, Bl, m0, n0, 0, K, tid);
    asm volatile("cp.async.commit_group;\n" ::: "memory");
    issue_stage(sb, 1, Ah, Al, Bh, Bl, m0, n0, BK, K, tid);
    asm volatile("cp.async.commit_group;\n" ::: "memory");

    // ldmatrix lane address components
    int a_row = ((lane >> 3) & 1) * 8 + (lane & 7);
    int a_k   = (lane >> 4) << 3;
    int b_row = ((lane >> 4) << 3) + (lane & 7);
    int b_k   = ((lane >> 3) & 1) << 3;

    int niter = K / BK;
    for (int it = 0; it < niter; it++) {
        asm volatile("cp.async.wait_group 1;\n" ::: "memory");
        __syncthreads();
        int stage = it & 1;
        uint32_t st = sb + stage * STAGE_BYTES;
        #pragma unroll
        for (int pass = 0; pass < 3; pass++) {
            uint32_t baseA = st + ((pass == 2) ? TILE_BYTES : 0);
            uint32_t baseB = st + 2 * TILE_BYTES + ((pass == 1) ? TILE_BYTES : 0);
            #pragma unroll
            for (int ks = 0; ks < 2; ks++) {
                uint32_t ra[4][4], rb[2][4];
                #pragma unroll
                for (int i = 0; i < 4; i++)
                    ldsm4(ra[i],
                          baseA + ((wm + i * 16 + a_row) * SROW + ks * 16 + a_k) * 2);
                #pragma unroll
                for (int j2 = 0; j2 < 2; j2++)
                    ldsm4(rb[j2],
                          baseB + ((wn + j2 * 16 + b_row) * SROW + ks * 16 + b_k) * 2);
                #pragma unroll
                for (int i = 0; i < 4; i++) {
                    mma16816(acc[i][0], ra[i], &rb[0][0]);
                    mma16816(acc[i][1], ra[i], &rb[0][2]);
                    mma16816(acc[i][2], ra[i], &rb[1][0]);
                    mma16816(acc[i][3], ra[i], &rb[1][2]);
                }
            }
        }
        __syncthreads();
        if (it + 2 < niter)
            issue_stage(sb, stage, Ah, Al, Bh, Bl, m0, n0, (it + 2) * BK, K, tid);
        asm volatile("cp.async.commit_group;\n" ::: "memory");
    }

    // Epilogue: thread (g,tg) holds rows g,g+8, cols 2*tg..+1 of each m16n8 tile
    int g = lane >> 2, tg = (lane & 3) << 1;
    #pragma unroll
    for (int i = 0; i < 4; i++) {
        int r0 = m0 + wm + i * 16 + g;
        #pragma unroll
        for (int j = 0; j < 4; j++) {
            int col = n0 + wn + j * 8 + tg;
            float v00 = acc[i][j][0], v01 = acc[i][j][1];
            float v10 = acc[i][j][2], v11 = acc[i][j][3];
            if (bias) {
                float2 bb = *(const float2*)(bias + col);
                v00 += bb.x; v01 += bb.y; v10 += bb.x; v11 += bb.y;
            }
            if (relu) {
                v00 = fmaxf(v00, 0.f); v01 = fmaxf(v01, 0.f);
                v10 = fmaxf(v10, 0.f); v11 = fmaxf(v11, 0.f);
            }
            size_t o0 = (size_t)r0 * N + col;
            size_t o1 = o0 + (size_t)8 * N;
            if (res) {
                float2 r0v = *(const float2*)(res + o0);
                float2 r1v = *(const float2*)(res + o1);
                v00 += r0v.x; v01 += r0v.y; v10 += r1v.x; v11 += r1v.y;
            }
            *(float2*)(C + o0) = make_float2(v00, v01);
            *(float2*)(C + o1) = make_float2(v10, v11);
        }
    }
}

// ---------------------------------------------------------------------------
// Causal attention, flash-style (fp32 SIMT). Block = (b, h, 64-query tile).
// ---------------------------------------------------------------------------
#define ATT_SMEM ((4 * 64 * 68 + 192) * 4)

__global__ __launch_bounds__(256)
void k_attn(const float* __restrict__ Q, const float* __restrict__ Kx,
            const float* __restrict__ Vx, float* __restrict__ O)
{
    extern __shared__ __align__(16) float smA[];
    float* QsT  = smA;
    float* KsT  = smA + 64 * 68;
    float* Vs   = smA + 2 * 64 * 68;
    float* Ss   = smA + 3 * 64 * 68;
    float* mRow = smA + 4 * 64 * 68;
    float* sRow = mRow + 64;
    float* fRow = sRow + 64;

    int qt = blockIdx.x;
    int bh = blockIdx.y;
    int b = bh >> 4, h = bh & 15;
    int tid = threadIdx.x;
    int tx = tid & 15, ty = tid >> 4;
    size_t base = ((size_t)b * Tm) * Dm + h * HSm;

    for (int i = tid; i < 1024; i += 256) {
        int r = i >> 4, c = (i & 15) << 2;
        float4 qv = *(const float4*)(Q + base + (size_t)(qt * 64 + r) * Dm + c);
        QsT[(c + 0) * 68 + r] = qv.x * 0.125f;
        QsT[(c + 1) * 68 + r] = qv.y * 0.125f;
        QsT[(c + 2) * 68 + r] = qv.z * 0.125f;
        QsT[(c + 3) * 68 + r] = qv.w * 0.125f;
    }
    if (tid < 64) { mRow[tid] = -1e30f; sRow[tid] = 0.f; }

    float acc[4][4] = {};

    for (int kt = 0; kt <= qt; kt++) {
        __syncthreads();
        for (int i = tid; i < 1024; i += 256) {
            int r = i >> 4, c = (i & 15) << 2;
            float4 kv = *(const float4*)(Kx + base + (size_t)(kt * 64 + r) * Dm + c);
            KsT[(c + 0) * 68 + r] = kv.x;
            KsT[(c + 1) * 68 + r] = kv.y;
            KsT[(c + 2) * 68 + r] = kv.z;
            KsT[(c + 3) * 68 + r] = kv.w;
            float4 vv = *(const float4*)(Vx + base + (size_t)(kt * 64 + r) * Dm + c);
            *(float4*)&Vs[r * 68 + c] = vv;
        }
        __syncthreads();

        float sc[4][4] = {};
        #pragma unroll 8
        for (int e = 0; e < 64; e++) {
            float4 qv = *(const float4*)&QsT[e * 68 + (ty << 2)];
            float4 kv = *(const float4*)&KsT[e * 68 + (tx << 2)];
            sc[0][0] += qv.x * kv.x; sc[0][1] += qv.x * kv.y;
            sc[0][2] += qv.x * kv.z; sc[0][3] += qv.x * kv.w;
            sc[1][0] += qv.y * kv.x; sc[1][1] += qv.y * kv.y;
            sc[1][2] += qv.y * kv.z; sc[1][3] += qv.y * kv.w;
            sc[2][0] += qv.z * kv.x; sc[2][1] += qv.z * kv.y;
            sc[2][2] += qv.z * kv.z; sc[2][3] += qv.z * kv.w;
            sc[3][0] += qv.w * kv.x; sc[3][1] += qv.w * kv.y;
            sc[3][2] += qv.w * kv.z; sc[3][3] += qv.w * kv.w;
        }
        #pragma unroll
        for (int i = 0; i < 4; i++)
            *(float4*)&Ss[((ty << 2) + i) * 68 + (tx << 2)] =
                make_float4(sc[i][0], sc[i][1], sc[i][2], sc[i][3]);
        __syncthreads();

        if (tid < 64) {
            int r = tid;
            int lim = (kt == qt) ? r : 63;
            float mOld = mRow[r];
            float mx = mOld;
            for (int j = 0; j <= lim; j++) mx = fmaxf(mx, Ss[r * 68 + j]);
            float f = __expf(mOld - mx);
            float sum = sRow[r] * f;
            for (int j = 0; j < 64; j++) {
                float p = (j <= lim) ? __expf(Ss[r * 68 + j] - mx) : 0.f;
                Ss[r * 68 + j] = p;
                sum += p;
            }
            mRow[r] = mx; sRow[r] = sum; fRow[r] = f;
        }
        __syncthreads();

        float f0 = fRow[(ty << 2) + 0], f1 = fRow[(ty << 2) + 1];
        float f2 = fRow[(ty << 2) + 2], f3 = fRow[(ty << 2) + 3];
        #pragma unroll
        for (int j = 0; j < 4; j++) {
            acc[0][j] *= f0; acc[1][j] *= f1; acc[2][j] *= f2; acc[3][j] *= f3;
        }
        #pragma unroll 8
        for (int j = 0; j < 64; j++) {
            float4 vv = *(const float4*)&Vs[j * 68 + (tx << 2)];
            float p0 = Ss[((ty << 2) + 0) * 68 + j];
            float p1 = Ss[((ty << 2) + 1) * 68 + j];
            float p2 = Ss[((ty << 2) + 2) * 68 + j];
            float p3 = Ss[((ty << 2) + 3) * 68 + j];
            acc[0][0] += p0 * vv.x; acc[0][1] += p0 * vv.y;
            acc[0][2] += p0 * vv.z; acc[0][3] += p0 * vv.w;
            acc[1][0] += p1 * vv.x; acc[1][1] += p1 * vv.y;
            acc[1][2] += p1 * vv.z; acc[1][3] += p1 * vv.w;
            acc[2][0] += p2 * vv.x; acc[2][1] += p2 * vv.y;
            acc[2][2] += p2 * vv.z; acc[2][3] += p2 * vv.w;
            acc[3][0] += p3 * vv.x; acc[3][1] += p3 * vv.y;
            acc[3][2] += p3 * vv.z; acc[3][3] += p3 * vv.w;
        }
    }

    #pragma unroll
    for (int i = 0; i < 4; i++) {
        float inv = 1.0f / sRow[(ty << 2) + i];
        size_t off = base + (size_t)(qt * 64 + (ty << 2) + i) * Dm + (tx << 2);
        *(float4*)(O + off) = make_float4(acc[i][0] * inv, acc[i][1] * inv,
                                          acc[i][2] * inv, acc[i][3] * inv);
    }
}

// ---------------------------------------------------------------------------
// Host orchestration (graph-capturable: kernel launches only)
// ---------------------------------------------------------------------------
extern "C" void kernel_launch(void* const* d_in, const int* in_sizes, int n_in,
                              void* d_out, int out_size)
{
    (void)in_sizes; (void)n_in; (void)out_size;
    const int*   x      = (const int*)  d_in[0];
    const float* tok    = (const float*)d_in[1];
    const float* pos    = (const float*)d_in[2];
    const float* wq     = (const float*)d_in[3];
    const float* wk     = (const float*)d_in[4];
    const float* wv     = (const float*)d_in[5];
    const float* w_o    = (const float*)d_in[6];
    const float* b_o    = (const float*)d_in[7];
    const float* ln1_g  = (const float*)d_in[8];
    const float* ln1_b  = (const float*)d_in[9];
    const float* ln2_g  = (const float*)d_in[10];
    const float* ln2_b  = (const float*)d_in[11];
    const float* w1     = (const float*)d_in[12];
    const float* b1     = (const float*)d_in[13];
    const float* w2     = (const float*)d_in[14];
    const float* b2     = (const float*)d_in[15];
    const float* lnf_g  = (const float*)d_in[16];
    const float* lnf_b  = (const float*)d_in[17];
    const float* w_lm   = (const float*)d_in[18];
    const float* b_lm   = (const float*)d_in[19];
    float* out = (float*)d_out;

    float *hb, *hn, *qb, *kb, *vb, *ab, *ff;
    cudaGetSymbolAddress((void**)&hb, g_h);
    cudaGetSymbolAddress((void**)&hn, g_hn);
    cudaGetSymbolAddress((void**)&qb, g_q);
    cudaGetSymbolAddress((void**)&kb, g_k);
    cudaGetSymbolAddress((void**)&vb, g_v);
    cudaGetSymbolAddress((void**)&ab, g_att);
    cudaGetSymbolAddress((void**)&ff, g_ffn);

    __nv_bfloat16 *ah,*al,*qh,*ql,*kh,*kl,*vh,*vl,*oh,*ol,*w1h,*w1l,*w2h,*w2l,*lh,*ll;
    cudaGetSymbolAddress((void**)&ah, g_ah);  cudaGetSymbolAddress((void**)&al, g_al);
    cudaGetSymbolAddress((void**)&qh, g_qh);  cudaGetSymbolAddress((void**)&ql, g_ql);
    cudaGetSymbolAddress((void**)&kh, g_kh);  cudaGetSymbolAddress((void**)&kl, g_kl);
    cudaGetSymbolAddress((void**)&vh, g_vh);  cudaGetSymbolAddress((void**)&vl, g_vl);
    cudaGetSymbolAddress((void**)&oh, g_oh);  cudaGetSymbolAddress((void**)&ol, g_ol);
    cudaGetSymbolAddress((void**)&w1h, g_1h); cudaGetSymbolAddress((void**)&w1l, g_1l);
    cudaGetSymbolAddress((void**)&w2h, g_2h); cudaGetSymbolAddress((void**)&w2l, g_2l);
    cudaGetSymbolAddress((void**)&lh, g_lh);  cudaGetSymbolAddress((void**)&ll, g_ll);

    cudaFuncSetAttribute(k_attn, cudaFuncAttributeMaxDynamicSharedMemorySize, ATT_SMEM);
    cudaFuncSetAttribute(k_gemm_mma, cudaFuncAttributeMaxDynamicSharedMemorySize, GEMM_SMEM);

    dim3 g1(Dm / 128, Mrows / 128);    // N=1024
    dim3 g2(FFm / 128, Mrows / 128);   // N=4096
    dim3 gl(Vm / 128, Mrows / 128);    // N=8192
    dim3 ga(Tm / 64, Bm_ * Hm);
    int cad = Mrows * Dm / 1024;       // conv_a blocks for [Mrows, Dm]
    int caf = Mrows * FFm / 1024;      // conv_a blocks for [Mrows, FFm]

    k_embed<<<Mrows, 256>>>(x, tok, pos, hb);

    for (int l = 0; l < Lm; l++) {
        size_t wofs = (size_t)l * Hm * Dm * HSm;
        k_ln<<<Mrows, 256>>>(hb, ln1_g + l * Dm, ln1_b + l * Dm, hn);
        k_conv_a<<<cad, 256>>>(hn, ah, al);
        k_conv_qkv<<<dim3(16, 16, 3), 256>>>(wq + wofs, wk + wofs, wv + wofs,
                                             qh, ql, kh, kl, vh, vl);
        k_gemm_mma<<<g1, 256, GEMM_SMEM>>>(ah, al, qh, ql, nullptr, nullptr, qb,
                                           Mrows, Dm, Dm, 0);
        k_gemm_mma<<<g1, 256, GEMM_SMEM>>>(ah, al, kh, kl, nullptr, nullptr, kb,
                                           Mrows, Dm, Dm, 0);
        k_gemm_mma<<<g1, 256, GEMM_SMEM>>>(ah, al, vh, vl, nullptr, nullptr, vb,
                                           Mrows, Dm, Dm, 0);
        k_attn<<<ga, 256, ATT_SMEM>>>(qb, kb, vb, ab);

        k_conv_a<<<cad, 256>>>(ab, ah, al);
        k_conv_t<<<dim3(16, 16), 256>>>(w_o + (size_t)l * Dm * Dm, oh, ol, Dm, Dm);
        // h = hn + att @ w_o + b_o
        k_gemm_mma<<<g1, 256, GEMM_SMEM>>>(ah, al, oh, ol, b_o + l * Dm, hn, hb,
                                           Mrows, Dm, Dm, 0);
        k_ln<<<Mrows, 256>>>(hb, ln2_g + l * Dm, ln2_b + l * Dm, hn);
        k_conv_a<<<cad, 256>>>(hn, ah, al);

        k_conv_t<<<dim3(64, 16), 256>>>(w1 + (size_t)l * Dm * FFm, w1h, w1l, Dm, FFm);
        k_gemm_mma<<<g2, 256, GEMM_SMEM>>>(ah, al, w1h, w1l, b1 + l * FFm, nullptr,
                                           ff, Mrows, FFm, Dm, 1);
        k_conv_a<<<caf, 256>>>(ff, ah, al);
        k_conv_t<<<dim3(16, 64), 256>>>(w2 + (size_t)l * FFm * Dm, w2h, w2l, FFm, Dm);
        // h = hn + ffn1 @ w2 + b2
        k_gemm_mma<<<g1, 256, GEMM_SMEM>>>(ah, al, w2h, w2l, b2 + l * Dm, hn, hb,
                                           Mrows, Dm, FFm, 0);
    }

    k_ln<<<Mrows, 256>>>(hb, lnf_g, lnf_b, hn);
    k_conv_a<<<cad, 256>>>(hn, ah, al);
    k_conv_t<<<dim3(128, 16), 256>>>(w_lm, lh, ll, Dm, Vm);
    k_gemm_mma<<<gl, 256, GEMM_SMEM>>>(ah, al, lh, ll, b_lm, nullptr, out,
                                       Mrows, Vm, Dm, 0);
}

// round 8
// speedup vs baseline: 2.0986x; 1.0489x over previous
#include <cuda_runtime.h>
#include <cuda_bf16.h>
#include <cstdint>

// ---------------------------------------------------------------------------
// GPT-style transformer forward. GEMMs on tensor cores via mma.sync (bf16x3
// split for fp32-like accuracy); attention fp32 flash-style SIMT.
// B=4, T=1024, D=1024, H=16, HS=64, L=8, FF=4096, V=8192
// ---------------------------------------------------------------------------

#define Dm   1024
#define FFm  4096
#define Vm   8192
#define Hm   16
#define HSm  64
#define Lm   8
#define Bm_  4
#define Tm   1024
#define Mrows (Bm_ * Tm)   // 4096
#define QKVN 3072

// fp32 activation scratch
__device__ float g_h  [Mrows * Dm];
__device__ float g_hn [Mrows * Dm];
__device__ float g_qkv[Mrows * QKVN];

// bf16 split activation scratch
__device__ __nv_bfloat16 g_ah[Mrows * Dm],  g_al[Mrows * Dm];
__device__ __nv_bfloat16 g_fh[Mrows * FFm], g_fl[Mrows * FFm];

// bf16 split weight scratch ([N][K] transposed layout), reused per layer
__device__ __nv_bfloat16 g_wqkvh[QKVN * Dm], g_wqkvl[QKVN * Dm];
__device__ __nv_bfloat16 g_oh[Dm * Dm],  g_ol[Dm * Dm];
__device__ __nv_bfloat16 g_1h[Dm * FFm], g_1l[Dm * FFm];
__device__ __nv_bfloat16 g_2h[Dm * FFm], g_2l[Dm * FFm];
__device__ __nv_bfloat16 g_lh[Dm * Vm],  g_ll[Dm * Vm];

// ---------------------------------------------------------------------------
// helpers
// ---------------------------------------------------------------------------
__device__ __forceinline__ uint32_t smem_u32(const void* p) {
    uint32_t a;
    asm("{ .reg .u64 t; cvta.to.shared.u64 t, %1; cvt.u32.u64 %0, t; }"
        : "=r"(a) : "l"(p));
    return a;
}

__device__ __forceinline__ void split_bf16(float f, __nv_bfloat16& h, __nv_bfloat16& l) {
    h = __float2bfloat16(f);
    l = __float2bfloat16(f - __bfloat162float(h));
}

__device__ __forceinline__ void ldsm4(uint32_t* r, uint32_t addr) {
    asm volatile("ldmatrix.sync.aligned.m8n8.x4.shared.b16 {%0,%1,%2,%3}, [%4];\n"
                 : "=r"(r[0]), "=r"(r[1]), "=r"(r[2]), "=r"(r[3]) : "r"(addr));
}

__device__ __forceinline__ void mma16816(float* c, const uint32_t* a, const uint32_t* b) {
    asm volatile(
        "mma.sync.aligned.m16n8k16.row.col.f32.bf16.bf16.f32 "
        "{%0,%1,%2,%3}, {%4,%5,%6,%7}, {%8,%9}, {%0,%1,%2,%3};\n"
        : "+f"(c[0]), "+f"(c[1]), "+f"(c[2]), "+f"(c[3])
        : "r"(a[0]), "r"(a[1]), "r"(a[2]), "r"(a[3]), "r"(b[0]), "r"(b[1]));
}

// ---------------------------------------------------------------------------
// Embedding: h[row] = tok_embd[x[row]] + pos_embd[x[row]]   (pos quirk!)
// ---------------------------------------------------------------------------
__global__ void k_embed(const int* __restrict__ x, const float* __restrict__ tok,
                        const float* __restrict__ pos, float* __restrict__ out)
{
    int row = blockIdx.x;
    int t = x[row];
    const float4* te = (const float4*)(tok + (size_t)t * Dm);
    const float4* pe = (const float4*)(pos + (size_t)t * Dm);
    float4* o = (float4*)(out + (size_t)row * Dm);
    int i = threadIdx.x;
    float4 a = te[i], b = pe[i];
    o[i] = make_float4(a.x + b.x, a.y + b.y, a.z + b.z, a.w + b.w);
}

// ---------------------------------------------------------------------------
// LayerNorm over D=1024 + fused bf16 hi/lo split of the output.
// ---------------------------------------------------------------------------
__global__ void k_ln(const float* __restrict__ in, const float* __restrict__ gw,
                     const float* __restrict__ bw, float* __restrict__ out,
                     __nv_bfloat16* __restrict__ oh, __nv_bfloat16* __restrict__ ol)
{
    __shared__ float red[8];
    int row = blockIdx.x;
    int c = threadIdx.x * 4;
    const float* xr = in + (size_t)row * Dm;
    float4 xv = *(const float4*)(xr + c);
    float s = xv.x + xv.y + xv.z + xv.w;
    #pragma unroll
    for (int o = 16; o; o >>= 1) s += __shfl_xor_sync(0xffffffffu, s, o);
    int wid = threadIdx.x >> 5, lid = threadIdx.x & 31;
    if (lid == 0) red[wid] = s;
    __syncthreads();
    float tot = 0.f;
    #pragma unroll
    for (int i = 0; i < 8; i++) tot += red[i];
    float mean = tot * (1.0f / Dm);
    float d0 = xv.x - mean, d1 = xv.y - mean, d2 = xv.z - mean, d3 = xv.w - mean;
    float s2 = d0*d0 + d1*d1 + d2*d2 + d3*d3;
    __syncthreads();
    #pragma unroll
    for (int o = 16; o; o >>= 1) s2 += __shfl_xor_sync(0xffffffffu, s2, o);
    if (lid == 0) red[wid] = s2;
    __syncthreads();
    float v2 = 0.f;
    #pragma unroll
    for (int i = 0; i < 8; i++) v2 += red[i];
    float rstd = rsqrtf(v2 * (1.0f / Dm) + 1e-5f);
    float4 gv = *(const float4*)(gw + c);
    float4 bv = *(const float4*)(bw + c);
    float4 ov = make_float4(d0 * rstd * gv.x + bv.x, d1 * rstd * gv.y + bv.y,
                            d2 * rstd * gv.z + bv.z, d3 * rstd * gv.w + bv.w);
    size_t off = (size_t)row * Dm + c;
    *(float4*)(out + off) = ov;
    __nv_bfloat16 h0, l0, h1, l1, h2, l2, h3, l3;
    split_bf16(ov.x, h0, l0); split_bf16(ov.y, h1, l1);
    split_bf16(ov.z, h2, l2); split_bf16(ov.w, h3, l3);
    *(__nv_bfloat162*)(oh + off)     = __halves2bfloat162(h0, h1);
    *(__nv_bfloat162*)(oh + off + 2) = __halves2bfloat162(h2, h3);
    *(__nv_bfloat162*)(ol + off)     = __halves2bfloat162(l0, l1);
    *(__nv_bfloat162*)(ol + off + 2) = __halves2bfloat162(l2, l3);
}

// ---------------------------------------------------------------------------
// Weight convert: qkv (H,D,HS) -> packed [3072][1024] bf16 hi/lo
// rows 0..1023 = Q heads, 1024..2047 = K, 2048..3071 = V
// ---------------------------------------------------------------------------
__global__ void k_conv_qkv(const float* __restrict__ wq, const float* __restrict__ wk,
                           const float* __restrict__ wv,
                           __nv_bfloat16* __restrict__ oh,
                           __nv_bfloat16* __restrict__ ol)
{
    __shared__ float t[64][65];
    int h = blockIdx.y;
    int d0 = blockIdx.x << 6;
    int m = blockIdx.z;
    const float* src = (m == 0) ? wq : (m == 1) ? wk : wv;

    const float* base = src + ((size_t)h << 16) + ((size_t)d0 << 6);
    for (int i = threadIdx.x; i < 1024; i += 256) {
        int di = i >> 4, e4 = (i & 15) << 2;
        float4 v = *(const float4*)(base + ((size_t)di << 6) + e4);
        t[di][e4] = v.x; t[di][e4+1] = v.y; t[di][e4+2] = v.z; t[di][e4+3] = v.w;
    }
    __syncthreads();
    for (int i = threadIdx.x; i < 2048; i += 256) {
        int e = i >> 5, d2 = (i & 31) << 1;
        __nv_bfloat16 h0, l0, h1, l1;
        split_bf16(t[d2][e], h0, l0);
        split_bf16(t[d2 + 1][e], h1, l1);
        size_t off = ((size_t)(m * 1024 + h * 64 + e) << 10) + d0 + d2;
        *(__nv_bfloat162*)(oh + off) = __halves2bfloat162(h0, h1);
        *(__nv_bfloat162*)(ol + off) = __halves2bfloat162(l0, l1);
    }
}

// ---------------------------------------------------------------------------
// Weight convert (transpose): in [Kd,Nd] fp32 -> out [Nd][Kd] bf16 hi/lo
// ---------------------------------------------------------------------------
__global__ void k_conv_t(const float* __restrict__ in,
                         __nv_bfloat16* __restrict__ oh,
                         __nv_bfloat16* __restrict__ ol, int Kd, int Nd)
{
    __shared__ float t[64][65];
    int k0 = blockIdx.y << 6, n0 = blockIdx.x << 6;
    for (int i = threadIdx.x; i < 1024; i += 256) {
        int r = i >> 4, c4 = (i & 15) << 2;
        float4 v = *(const float4*)(in + (size_t)(k0 + r) * Nd + n0 + c4);
        t[r][c4] = v.x; t[r][c4+1] = v.y; t[r][c4+2] = v.z; t[r][c4+3] = v.w;
    }
    __syncthreads();
    for (int i = threadIdx.x; i < 2048; i += 256) {
        int n = i >> 5, k2 = (i & 31) << 1;
        __nv_bfloat16 h0, l0, h1, l1;
        split_bf16(t[k2][n], h0, l0);
        split_bf16(t[k2 + 1][n], h1, l1);
        size_t off = (size_t)(n0 + n) * Kd + k0 + k2;
        *(__nv_bfloat162*)(oh + off) = __halves2bfloat162(h0, h1);
        *(__nv_bfloat162*)(ol + off) = __halves2bfloat162(l0, l1);
    }
}

// ---------------------------------------------------------------------------
// Tensor-core GEMM (mma.sync, bf16x3):
// C[M,N] = A[M,K] * B^T  (A as [M][K] hi/lo; B as [N][K] hi/lo)
// 128x128 CTA tile, BK=32, 256 threads, double-buffered cp.async.
// Output: fp32 C (with optional bias/relu/residual) OR bf16 hi/lo split.
// ---------------------------------------------------------------------------
#define BK 32
#define SROW 40                       // bf16 elems per smem row
#define TILE_BYTES (128 * SROW * 2)   // 10240
#define STAGE_BYTES (4 * TILE_BYTES)  // 40960
#define GEMM_SMEM (2 * STAGE_BYTES)   // 81920

__device__ __forceinline__ void issue_stage(
    uint32_t sb, int stage,
    const __nv_bfloat16* Ah, const __nv_bfloat16* Al,
    const __nv_bfloat16* Bh, const __nv_bfloat16* Bl,
    int m0, int n0, int kc, int K, int tid)
{
    uint32_t sbase = sb + stage * STAGE_BYTES;
    #pragma unroll
    for (int i = 0; i < 8; i++) {
        int id = (i << 8) + tid;          // 0..2047
        int tile = id >> 9;               // 0..3 : AH AL BH BL
        int r = (id >> 2) & 127;
        int c = id & 3;                   // 16B chunk within 64B row data
        const __nv_bfloat16* src =
            (tile == 0) ? Ah : (tile == 1) ? Al : (tile == 2) ? Bh : Bl;
        int rowg = ((tile < 2) ? m0 : n0) + r;
        const void* g = src + (size_t)rowg * K + kc + (c << 3);
        uint32_t s = sbase + tile * TILE_BYTES + r * (SROW * 2) + (c << 4);
        asm volatile("cp.async.cg.shared.global [%0], [%1], 16;\n"
                     :: "r"(s), "l"(g));
    }
}

__global__ __launch_bounds__(256, 2)
void k_gemm_mma(const __nv_bfloat16* __restrict__ Ah, const __nv_bfloat16* __restrict__ Al,
                const __nv_bfloat16* __restrict__ Bh, const __nv_bfloat16* __restrict__ Bl,
                const float* __restrict__ bias, const float* __restrict__ res,
                float* __restrict__ C,
                __nv_bfloat16* __restrict__ Ch, __nv_bfloat16* __restrict__ Cl,
                int M, int N, int K, int relu)
{
    extern __shared__ __align__(128) char sm2[];
    uint32_t sb = smem_u32(sm2);
    int tid = threadIdx.x;
    int lane = tid & 31, wid = tid >> 5;
    int wm = (wid & 1) << 6;    // warp M offset (0/64)
    int wn = (wid >> 1) << 5;   // warp N offset (0/32/64/96)
    int m0 = blockIdx.y << 7, n0 = blockIdx.x << 7;

    float acc[4][4][4];
    #pragma unroll
    for (int i = 0; i < 4; i++)
        #pragma unroll
        for (int j = 0; j < 4; j++)
            #pragma unroll
            for (int k = 0; k < 4; k++) acc[i][j][k] = 0.f;

    issue_stage(sb, 0, Ah, Al, Bh, Bl, m0, n0, 0, K, tid);
    asm volatile("cp.async.commit_group;\n" ::: "memory");
    issue_stage(sb, 1, Ah, Al, Bh, Bl, m0, n0, BK, K, tid);
    asm volatile("cp.async.commit_group;\n" ::: "memory");

    // ldmatrix lane address components
    int a_row = ((lane >> 3) & 1) * 8 + (lane & 7);
    int a_k   = (lane >> 4) << 3;
    int b_row = ((lane >> 4) << 3) + (lane & 7);
    int b_k   = ((lane >> 3) & 1) << 3;

    int niter = K / BK;
    for (int it = 0; it < niter; it++) {
        asm volatile("cp.async.wait_group 1;\n" ::: "memory");
        __syncthreads();
        int stage = it & 1;
        uint32_t st = sb + stage * STAGE_BYTES;
        #pragma unroll
        for (int ks = 0; ks < 2; ks++) {
            uint32_t ra[4][4], rbh[2][4], rbl[2][4];
            // A-hi
            #pragma unroll
            for (int i = 0; i < 4; i++)
                ldsm4(ra[i], st + ((wm + i * 16 + a_row) * SROW + ks * 16 + a_k) * 2);
            // B-hi, B-lo
            #pragma unroll
            for (int j2 = 0; j2 < 2; j2++) {
                uint32_t boff = ((wn + j2 * 16 + b_row) * SROW + ks * 16 + b_k) * 2;
                ldsm4(rbh[j2], st + 2 * TILE_BYTES + boff);
                ldsm4(rbl[j2], st + 3 * TILE_BYTES + boff);
            }
            // pass 0: Ah * Bh
            #pragma unroll
            for (int i = 0; i < 4; i++) {
                mma16816(acc[i][0], ra[i], &rbh[0][0]);
                mma16816(acc[i][1], ra[i], &rbh[0][2]);
                mma16816(acc[i][2], ra[i], &rbh[1][0]);
                mma16816(acc[i][3], ra[i], &rbh[1][2]);
            }
            // pass 1: Ah * Bl
            #pragma unroll
            for (int i = 0; i < 4; i++) {
                mma16816(acc[i][0], ra[i], &rbl[0][0]);
                mma16816(acc[i][1], ra[i], &rbl[0][2]);
                mma16816(acc[i][2], ra[i], &rbl[1][0]);
                mma16816(acc[i][3], ra[i], &rbl[1][2]);
            }
            // A-lo (reuse ra regs)
            #pragma unroll
            for (int i = 0; i < 4; i++)
                ldsm4(ra[i], st + TILE_BYTES +
                      ((wm + i * 16 + a_row) * SROW + ks * 16 + a_k) * 2);
            // pass 2: Al * Bh
            #pragma unroll
            for (int i = 0; i < 4; i++) {
                mma16816(acc[i][0], ra[i], &rbh[0][0]);
                mma16816(acc[i][1], ra[i], &rbh[0][2]);
                mma16816(acc[i][2], ra[i], &rbh[1][0]);
                mma16816(acc[i][3], ra[i], &rbh[1][2]);
            }
        }
        __syncthreads();
        if (it + 2 < niter)
            issue_stage(sb, stage, Ah, Al, Bh, Bl, m0, n0, (it + 2) * BK, K, tid);
        asm volatile("cp.async.commit_group;\n" ::: "memory");
    }

    // Epilogue: thread (g,tg) holds rows g,g+8, cols 2*tg..+1 of each m16n8 tile
    int g = lane >> 2, tg = (lane & 3) << 1;
    #pragma unroll
    for (int i = 0; i < 4; i++) {
        int r0 = m0 + wm + i * 16 + g;
        #pragma unroll
        for (int j = 0; j < 4; j++) {
            int col = n0 + wn + j * 8 + tg;
            float v00 = acc[i][j][0], v01 = acc[i][j][1];
            float v10 = acc[i][j][2], v11 = acc[i][j][3];
            if (bias) {
                float2 bb = *(const float2*)(bias + col);
                v00 += bb.x; v01 += bb.y; v10 += bb.x; v11 += bb.y;
            }
            if (relu) {
                v00 = fmaxf(v00, 0.f); v01 = fmaxf(v01, 0.f);
                v10 = fmaxf(v10, 0.f); v11 = fmaxf(v11, 0.f);
            }
            size_t o0 = (size_t)r0 * N + col;
            size_t o1 = o0 + (size_t)8 * N;
            if (Ch) {
                __nv_bfloat16 h0, l0, h1, l1;
                split_bf16(v00, h0, l0); split_bf16(v01, h1, l1);
                *(__nv_bfloat162*)(Ch + o0) = __halves2bfloat162(h0, h1);
                *(__nv_bfloat162*)(Cl + o0) = __halves2bfloat162(l0, l1);
                split_bf16(v10, h0, l0); split_bf16(v11, h1, l1);
                *(__nv_bfloat162*)(Ch + o1) = __halves2bfloat162(h0, h1);
                *(__nv_bfloat162*)(Cl + o1) = __halves2bfloat162(l0, l1);
            } else {
                if (res) {
                    float2 r0v = *(const float2*)(res + o0);
                    float2 r1v = *(const float2*)(res + o1);
                    v00 += r0v.x; v01 += r0v.y; v10 += r1v.x; v11 += r1v.y;
                }
                *(float2*)(C + o0) = make_float2(v00, v01);
                *(float2*)(C + o1) = make_float2(v10, v11);
            }
        }
    }
}

// ---------------------------------------------------------------------------
// Causal attention, flash-style (fp32 SIMT). Block = (b, h, 64-query tile).
// Reads packed qkv [M][3072]; writes bf16 hi/lo split output [M][1024].
// ---------------------------------------------------------------------------
#define ATT_SMEM ((4 * 64 * 68 + 192) * 4)

__global__ __launch_bounds__(256)
void k_attn(const float* __restrict__ QKV,
            __nv_bfloat16* __restrict__ Oh, __nv_bfloat16* __restrict__ Ol)
{
    extern __shared__ __align__(16) float smA[];
    float* QsT  = smA;
    float* KsT  = smA + 64 * 68;
    float* Vs   = smA + 2 * 64 * 68;
    float* Ss   = smA + 3 * 64 * 68;
    float* mRow = smA + 4 * 64 * 68;
    float* sRow = mRow + 64;
    float* fRow = sRow + 64;

    int qt = blockIdx.x;
    int bh = blockIdx.y;
    int b = bh >> 4, h = bh & 15;
    int tid = threadIdx.x;
    int tx = tid & 15, ty = tid >> 4;
    size_t rbase = (size_t)b * Tm;     // row base
    const float* Q  = QKV + h * HSm;
    const float* Kx = QKV + 1024 + h * HSm;
    const float* Vx = QKV + 2048 + h * HSm;

    for (int i = tid; i < 1024; i += 256) {
        int r = i >> 4, c = (i & 15) << 2;
        float4 qv = *(const float4*)(Q + (rbase + qt * 64 + r) * QKVN + c);
        QsT[(c + 0) * 68 + r] = qv.x * 0.125f;
        QsT[(c + 1) * 68 + r] = qv.y * 0.125f;
        QsT[(c + 2) * 68 + r] = qv.z * 0.125f;
        QsT[(c + 3) * 68 + r] = qv.w * 0.125f;
    }
    if (tid < 64) { mRow[tid] = -1e30f; sRow[tid] = 0.f; }

    float acc[4][4] = {};

    for (int kt = 0; kt <= qt; kt++) {
        __syncthreads();
        for (int i = tid; i < 1024; i += 256) {
            int r = i >> 4, c = (i & 15) << 2;
            float4 kv = *(const float4*)(Kx + (rbase + kt * 64 + r) * QKVN + c);
            KsT[(c + 0) * 68 + r] = kv.x;
            KsT[(c + 1) * 68 + r] = kv.y;
            KsT[(c + 2) * 68 + r] = kv.z;
            KsT[(c + 3) * 68 + r] = kv.w;
            float4 vv = *(const float4*)(Vx + (rbase + kt * 64 + r) * QKVN + c);
            *(float4*)&Vs[r * 68 + c] = vv;
        }
        __syncthreads();

        float sc[4][4] = {};
        #pragma unroll 8
        for (int e = 0; e < 64; e++) {
            float4 qv = *(const float4*)&QsT[e * 68 + (ty << 2)];
            float4 kv = *(const float4*)&KsT[e * 68 + (tx << 2)];
            sc[0][0] += qv.x * kv.x; sc[0][1] += qv.x * kv.y;
            sc[0][2] += qv.x * kv.z; sc[0][3] += qv.x * kv.w;
            sc[1][0] += qv.y * kv.x; sc[1][1] += qv.y * kv.y;
            sc[1][2] += qv.y * kv.z; sc[1][3] += qv.y * kv.w;
            sc[2][0] += qv.z * kv.x; sc[2][1] += qv.z * kv.y;
            sc[2][2] += qv.z * kv.z; sc[2][3] += qv.z * kv.w;
            sc[3][0] += qv.w * kv.x; sc[3][1] += qv.w * kv.y;
            sc[3][2] += qv.w * kv.z; sc[3][3] += qv.w * kv.w;
        }
        #pragma unroll
        for (int i = 0; i < 4; i++)
            *(float4*)&Ss[((ty << 2) + i) * 68 + (tx << 2)] =
                make_float4(sc[i][0], sc[i][1], sc[i][2], sc[i][3]);
        __syncthreads();

        if (tid < 64) {
            int r = tid;
            int lim = (kt == qt) ? r : 63;
            float mOld = mRow[r];
            float mx = mOld;
            for (int j = 0; j <= lim; j++) mx = fmaxf(mx, Ss[r * 68 + j]);
            float f = __expf(mOld - mx);
            float sum = sRow[r] * f;
            for (int j = 0; j < 64; j++) {
                float p = (j <= lim) ? __expf(Ss[r * 68 + j] - mx) : 0.f;
                Ss[r * 68 + j] = p;
                sum += p;
            }
            mRow[r] = mx; sRow[r] = sum; fRow[r] = f;
        }
        __syncthreads();

        float f0 = fRow[(ty << 2) + 0], f1 = fRow[(ty << 2) + 1];
        float f2 = fRow[(ty << 2) + 2], f3 = fRow[(ty << 2) + 3];
        #pragma unroll
        for (int j = 0; j < 4; j++) {
            acc[0][j] *= f0; acc[1][j] *= f1; acc[2][j] *= f2; acc[3][j] *= f3;
        }
        #pragma unroll 8
        for (int j = 0; j < 64; j++) {
            float4 vv = *(const float4*)&Vs[j * 68 + (tx << 2)];
            float p0 = Ss[((ty << 2) + 0) * 68 + j];
            float p1 = Ss[((ty << 2) + 1) * 68 + j];
            float p2 = Ss[((ty << 2) + 2) * 68 + j];
            float p3 = Ss[((ty << 2) + 3) * 68 + j];
            acc[0][0] += p0 * vv.x; acc[0][1] += p0 * vv.y;
            acc[0][2] += p0 * vv.z; acc[0][3] += p0 * vv.w;
            acc[1][0] += p1 * vv.x; acc[1][1] += p1 * vv.y;
            acc[1][2] += p1 * vv.z; acc[1][3] += p1 * vv.w;
            acc[2][0] += p2 * vv.x; acc[2][1] += p2 * vv.y;
            acc[2][2] += p2 * vv.z; acc[2][3] += p2 * vv.w;
            acc[3][0] += p3 * vv.x; acc[3][1] += p3 * vv.y;
            acc[3][2] += p3 * vv.z; acc[3][3] += p3 * vv.w;
        }
    }

    #pragma unroll
    for (int i = 0; i < 4; i++) {
        float inv = 1.0f / sRow[(ty << 2) + i];
        size_t off = (rbase + qt * 64 + (ty << 2) + i) * Dm + h * HSm + (tx << 2);
        float v0 = acc[i][0] * inv, v1 = acc[i][1] * inv;
        float v2 = acc[i][2] * inv, v3 = acc[i][3] * inv;
        __nv_bfloat16 h0, l0, h1, l1, h2, l2, h3, l3;
        split_bf16(v0, h0, l0); split_bf16(v1, h1, l1);
        split_bf16(v2, h2, l2); split_bf16(v3, h3, l3);
        *(__nv_bfloat162*)(Oh + off)     = __halves2bfloat162(h0, h1);
        *(__nv_bfloat162*)(Oh + off + 2) = __halves2bfloat162(h2, h3);
        *(__nv_bfloat162*)(Ol + off)     = __halves2bfloat162(l0, l1);
        *(__nv_bfloat162*)(Ol + off + 2) = __halves2bfloat162(l2, l3);
    }
}

// ---------------------------------------------------------------------------
// Host orchestration (graph-capturable: kernel launches only)
// ---------------------------------------------------------------------------
extern "C" void kernel_launch(void* const* d_in, const int* in_sizes, int n_in,
                              void* d_out, int out_size)
{
    (void)in_sizes; (void)n_in; (void)out_size;
    const int*   x      = (const int*)  d_in[0];
    const float* tok    = (const float*)d_in[1];
    const float* pos    = (const float*)d_in[2];
    const float* wq     = (const float*)d_in[3];
    const float* wk     = (const float*)d_in[4];
    const float* wv     = (const float*)d_in[5];
    const float* w_o    = (const float*)d_in[6];
    const float* b_o    = (const float*)d_in[7];
    const float* ln1_g  = (const float*)d_in[8];
    const float* ln1_b  = (const float*)d_in[9];
    const float* ln2_g  = (const float*)d_in[10];
    const float* ln2_b  = (const float*)d_in[11];
    const float* w1     = (const float*)d_in[12];
    const float* b1     = (const float*)d_in[13];
    const float* w2     = (const float*)d_in[14];
    const float* b2     = (const float*)d_in[15];
    const float* lnf_g  = (const float*)d_in[16];
    const float* lnf_b  = (const float*)d_in[17];
    const float* w_lm   = (const float*)d_in[18];
    const float* b_lm   = (const float*)d_in[19];
    float* out = (float*)d_out;

    float *hb, *hn, *qkvb;
    cudaGetSymbolAddress((void**)&hb, g_h);
    cudaGetSymbolAddress((void**)&hn, g_hn);
    cudaGetSymbolAddress((void**)&qkvb, g_qkv);

    __nv_bfloat16 *ah,*al,*fh,*fl,*wqkvh,*wqkvl,*oh,*ol,*w1h,*w1l,*w2h,*w2l,*lh,*ll;
    cudaGetSymbolAddress((void**)&ah, g_ah);       cudaGetSymbolAddress((void**)&al, g_al);
    cudaGetSymbolAddress((void**)&fh, g_fh);       cudaGetSymbolAddress((void**)&fl, g_fl);
    cudaGetSymbolAddress((void**)&wqkvh, g_wqkvh); cudaGetSymbolAddress((void**)&wqkvl, g_wqkvl);
    cudaGetSymbolAddress((void**)&oh, g_oh);       cudaGetSymbolAddress((void**)&ol, g_ol);
    cudaGetSymbolAddress((void**)&w1h, g_1h);      cudaGetSymbolAddress((void**)&w1l, g_1l);
    cudaGetSymbolAddress((void**)&w2h, g_2h);      cudaGetSymbolAddress((void**)&w2l, g_2l);
    cudaGetSymbolAddress((void**)&lh, g_lh);       cudaGetSymbolAddress((void**)&ll, g_ll);

    cudaFuncSetAttribute(k_attn, cudaFuncAttributeMaxDynamicSharedMemorySize, ATT_SMEM);
    cudaFuncSetAttribute(k_gemm_mma, cudaFuncAttributeMaxDynamicSharedMemorySize, GEMM_SMEM);

    dim3 g1(Dm / 128, Mrows / 128);     // N=1024
    dim3 gq(QKVN / 128, Mrows / 128);   // N=3072
    dim3 g2(FFm / 128, Mrows / 128);    // N=4096
    dim3 gl(Vm / 128, Mrows / 128);     // N=8192
    dim3 ga(Tm / 64, Bm_ * Hm);

    k_embed<<<Mrows, 256>>>(x, tok, pos, hb);

    for (int l = 0; l < Lm; l++) {
        size_t wofs = (size_t)l * Hm * Dm * HSm;
        k_ln<<<Mrows, 256>>>(hb, ln1_g + l * Dm, ln1_b + l * Dm, hn, ah, al);
        k_conv_qkv<<<dim3(16, 16, 3), 256>>>(wq + wofs, wk + wofs, wv + wofs,
                                             wqkvh, wqkvl);
        k_gemm_mma<<<gq, 256, GEMM_SMEM>>>(ah, al, wqkvh, wqkvl, nullptr, nullptr,
                                           qkvb, nullptr, nullptr,
                                           Mrows, QKVN, Dm, 0);
        k_attn<<<ga, 256, ATT_SMEM>>>(qkvb, ah, al);

        k_conv_t<<<dim3(16, 16), 256>>>(w_o + (size_t)l * Dm * Dm, oh, ol, Dm, Dm);
        // h = hn + att @ w_o + b_o
        k_gemm_mma<<<g1, 256, GEMM_SMEM>>>(ah, al, oh, ol, b_o + l * Dm, hn, hb,
                                           nullptr, nullptr, Mrows, Dm, Dm, 0);
        k_ln<<<Mrows, 256>>>(hb, ln2_g + l * Dm, ln2_b + l * Dm, hn, ah, al);

        k_conv_t<<<dim3(64, 16), 256>>>(w1 + (size_t)l * Dm * FFm, w1h, w1l, Dm, FFm);
        // ffn1 = relu(hn @ w1 + b1)  -> split bf16 output directly
        k_gemm_mma<<<g2, 256, GEMM_SMEM>>>(ah, al, w1h, w1l, b1 + l * FFm, nullptr,
                                           nullptr, fh, fl, Mrows, FFm, Dm, 1);
        k_conv_t<<<dim3(16, 64), 256>>>(w2 + (size_t)l * FFm * Dm, w2h, w2l, FFm, Dm);
        // h = hn + ffn1 @ w2 + b2
        k_gemm_mma<<<g1, 256, GEMM_SMEM>>>(fh, fl, w2h, w2l, b2 + l * Dm, hn, hb,
                                           nullptr, nullptr, Mrows, Dm, FFm, 0);
    }

    k_ln<<<Mrows, 256>>>(hb, lnf_g, lnf_b, hn, ah, al);
    k_conv_t<<<dim3(128, 16), 256>>>(w_lm, lh, ll, Dm, Vm);
    k_gemm_mma<<<gl, 256, GEMM_SMEM>>>(ah, al, lh, ll, b_lm, nullptr, out,
                                       nullptr, nullptr, Mrows, Vm, Dm, 0);
}

// round 9
// speedup vs baseline: 2.1535x; 1.0262x over previous
#include <cuda_runtime.h>
#include <cuda_bf16.h>
#include <cstdint>

// ---------------------------------------------------------------------------
// GPT-style transformer forward. GEMMs on tensor cores via mma.sync (bf16x3
// split for fp32-like accuracy); attention fp32 flash-style SIMT.
// B=4, T=1024, D=1024, H=16, HS=64, L=8, FF=4096, V=8192
// ---------------------------------------------------------------------------

#define Dm   1024
#define FFm  4096
#define Vm   8192
#define Hm   16
#define HSm  64
#define Lm   8
#define Bm_  4
#define Tm   1024
#define Mrows (Bm_ * Tm)   // 4096
#define QKVN 3072

// fp32 activation scratch
__device__ float g_h  [Mrows * Dm];
__device__ float g_hn [Mrows * Dm];
__device__ float g_qkv[Mrows * QKVN];

// bf16 split activation scratch
__device__ __nv_bfloat16 g_ah[Mrows * Dm],  g_al[Mrows * Dm];
__device__ __nv_bfloat16 g_fh[Mrows * FFm], g_fl[Mrows * FFm];

// bf16 split weight scratch ([N][K] transposed layout), reused per layer
__device__ __nv_bfloat16 g_wqkvh[QKVN * Dm], g_wqkvl[QKVN * Dm];
__device__ __nv_bfloat16 g_oh[Dm * Dm],  g_ol[Dm * Dm];
__device__ __nv_bfloat16 g_1h[Dm * FFm], g_1l[Dm * FFm];
__device__ __nv_bfloat16 g_2h[Dm * FFm], g_2l[Dm * FFm];
__device__ __nv_bfloat16 g_lh[Dm * Vm],  g_ll[Dm * Vm];

// ---------------------------------------------------------------------------
// helpers
// ---------------------------------------------------------------------------
__device__ __forceinline__ uint32_t smem_u32(const void* p) {
    uint32_t a;
    asm("{ .reg .u64 t; cvta.to.shared.u64 t, %1; cvt.u32.u64 %0, t; }"
        : "=r"(a) : "l"(p));
    return a;
}

__device__ __forceinline__ void split_bf16(float f, __nv_bfloat16& h, __nv_bfloat16& l) {
    h = __float2bfloat16(f);
    l = __float2bfloat16(f - __bfloat162float(h));
}

__device__ __forceinline__ void ldsm4(uint32_t* r, uint32_t addr) {
    asm volatile("ldmatrix.sync.aligned.m8n8.x4.shared.b16 {%0,%1,%2,%3}, [%4];\n"
                 : "=r"(r[0]), "=r"(r[1]), "=r"(r[2]), "=r"(r[3]) : "r"(addr));
}

__device__ __forceinline__ void mma16816(float* c, const uint32_t* a, const uint32_t* b) {
    asm volatile(
        "mma.sync.aligned.m16n8k16.row.col.f32.bf16.bf16.f32 "
        "{%0,%1,%2,%3}, {%4,%5,%6,%7}, {%8,%9}, {%0,%1,%2,%3};\n"
        : "+f"(c[0]), "+f"(c[1]), "+f"(c[2]), "+f"(c[3])
        : "r"(a[0]), "r"(a[1]), "r"(a[2]), "r"(a[3]), "r"(b[0]), "r"(b[1]));
}

// ---------------------------------------------------------------------------
// Embedding: h[row] = tok_embd[x[row]] + pos_embd[x[row]]   (pos quirk!)
// ---------------------------------------------------------------------------
__global__ void k_embed(const int* __restrict__ x, const float* __restrict__ tok,
                        const float* __restrict__ pos, float* __restrict__ out)
{
    int row = blockIdx.x;
    int t = x[row];
    const float4* te = (const float4*)(tok + (size_t)t * Dm);
    const float4* pe = (const float4*)(pos + (size_t)t * Dm);
    float4* o = (float4*)(out + (size_t)row * Dm);
    int i = threadIdx.x;
    float4 a = te[i], b = pe[i];
    o[i] = make_float4(a.x + b.x, a.y + b.y, a.z + b.z, a.w + b.w);
}

// ---------------------------------------------------------------------------
// LayerNorm over D=1024 + fused bf16 hi/lo split of the output.
// ---------------------------------------------------------------------------
__global__ void k_ln(const float* __restrict__ in, const float* __restrict__ gw,
                     const float* __restrict__ bw, float* __restrict__ out,
                     __nv_bfloat16* __restrict__ oh, __nv_bfloat16* __restrict__ ol)
{
    __shared__ float red[8];
    int row = blockIdx.x;
    int c = threadIdx.x * 4;
    const float* xr = in + (size_t)row * Dm;
    float4 xv = *(const float4*)(xr + c);
    float s = xv.x + xv.y + xv.z + xv.w;
    #pragma unroll
    for (int o = 16; o; o >>= 1) s += __shfl_xor_sync(0xffffffffu, s, o);
    int wid = threadIdx.x >> 5, lid = threadIdx.x & 31;
    if (lid == 0) red[wid] = s;
    __syncthreads();
    float tot = 0.f;
    #pragma unroll
    for (int i = 0; i < 8; i++) tot += red[i];
    float mean = tot * (1.0f / Dm);
    float d0 = xv.x - mean, d1 = xv.y - mean, d2 = xv.z - mean, d3 = xv.w - mean;
    float s2 = d0*d0 + d1*d1 + d2*d2 + d3*d3;
    __syncthreads();
    #pragma unroll
    for (int o = 16; o; o >>= 1) s2 += __shfl_xor_sync(0xffffffffu, s2, o);
    if (lid == 0) red[wid] = s2;
    __syncthreads();
    float v2 = 0.f;
    #pragma unroll
    for (int i = 0; i < 8; i++) v2 += red[i];
    float rstd = rsqrtf(v2 * (1.0f / Dm) + 1e-5f);
    float4 gv = *(const float4*)(gw + c);
    float4 bv = *(const float4*)(bw + c);
    float4 ov = make_float4(d0 * rstd * gv.x + bv.x, d1 * rstd * gv.y + bv.y,
                            d2 * rstd * gv.z + bv.z, d3 * rstd * gv.w + bv.w);
    size_t off = (size_t)row * Dm + c;
    *(float4*)(out + off) = ov;
    __nv_bfloat16 h0, l0, h1, l1, h2, l2, h3, l3;
    split_bf16(ov.x, h0, l0); split_bf16(ov.y, h1, l1);
    split_bf16(ov.z, h2, l2); split_bf16(ov.w, h3, l3);
    *(__nv_bfloat162*)(oh + off)     = __halves2bfloat162(h0, h1);
    *(__nv_bfloat162*)(oh + off + 2) = __halves2bfloat162(h2, h3);
    *(__nv_bfloat162*)(ol + off)     = __halves2bfloat162(l0, l1);
    *(__nv_bfloat162*)(ol + off + 2) = __halves2bfloat162(l2, l3);
}

// ---------------------------------------------------------------------------
// Weight convert: qkv (H,D,HS) -> packed [3072][1024] bf16 hi/lo
// ---------------------------------------------------------------------------
__global__ void k_conv_qkv(const float* __restrict__ wq, const float* __restrict__ wk,
                           const float* __restrict__ wv,
                           __nv_bfloat16* __restrict__ oh,
                           __nv_bfloat16* __restrict__ ol)
{
    __shared__ float t[64][65];
    int h = blockIdx.y;
    int d0 = blockIdx.x << 6;
    int m = blockIdx.z;
    const float* src = (m == 0) ? wq : (m == 1) ? wk : wv;

    const float* base = src + ((size_t)h << 16) + ((size_t)d0 << 6);
    for (int i = threadIdx.x; i < 1024; i += 256) {
        int di = i >> 4, e4 = (i & 15) << 2;
        float4 v = *(const float4*)(base + ((size_t)di << 6) + e4);
        t[di][e4] = v.x; t[di][e4+1] = v.y; t[di][e4+2] = v.z; t[di][e4+3] = v.w;
    }
    __syncthreads();
    for (int i = threadIdx.x; i < 2048; i += 256) {
        int e = i >> 5, d2 = (i & 31) << 1;
        __nv_bfloat16 h0, l0, h1, l1;
        split_bf16(t[d2][e], h0, l0);
        split_bf16(t[d2 + 1][e], h1, l1);
        size_t off = ((size_t)(m * 1024 + h * 64 + e) << 10) + d0 + d2;
        *(__nv_bfloat162*)(oh + off) = __halves2bfloat162(h0, h1);
        *(__nv_bfloat162*)(ol + off) = __halves2bfloat162(l0, l1);
    }
}

// ---------------------------------------------------------------------------
// Weight convert (transpose): in [Kd,Nd] fp32 -> out [Nd][Kd] bf16 hi/lo
// ---------------------------------------------------------------------------
__global__ void k_conv_t(const float* __restrict__ in,
                         __nv_bfloat16* __restrict__ oh,
                         __nv_bfloat16* __restrict__ ol, int Kd, int Nd)
{
    __shared__ float t[64][65];
    int k0 = blockIdx.y << 6, n0 = blockIdx.x << 6;
    for (int i = threadIdx.x; i < 1024; i += 256) {
        int r = i >> 4, c4 = (i & 15) << 2;
        float4 v = *(const float4*)(in + (size_t)(k0 + r) * Nd + n0 + c4);
        t[r][c4] = v.x; t[r][c4+1] = v.y; t[r][c4+2] = v.z; t[r][c4+3] = v.w;
    }
    __syncthreads();
    for (int i = threadIdx.x; i < 2048; i += 256) {
        int n = i >> 5, k2 = (i & 31) << 1;
        __nv_bfloat16 h0, l0, h1, l1;
        split_bf16(t[k2][n], h0, l0);
        split_bf16(t[k2 + 1][n], h1, l1);
        size_t off = (size_t)(n0 + n) * Kd + k0 + k2;
        *(__nv_bfloat162*)(oh + off) = __halves2bfloat162(h0, h1);
        *(__nv_bfloat162*)(ol + off) = __halves2bfloat162(l0, l1);
    }
}

// ---------------------------------------------------------------------------
// Tensor-core GEMM (mma.sync, bf16x3):
// C[M,N] = A[M,K] * B^T  (A as [M][K] hi/lo; B as [N][K] hi/lo)
// 128x128 CTA tile, BK=32, 128 threads (4 warps, 64x64 warp tiles),
// double-buffered cp.async. Output: fp32 (bias/relu/res) OR bf16 split.
// ---------------------------------------------------------------------------
#define BK 32
#define SROW 40                       // bf16 elems per smem row
#define TILE_BYTES (128 * SROW * 2)   // 10240
#define STAGE_BYTES (4 * TILE_BYTES)  // 40960
#define GEMM_SMEM (2 * STAGE_BYTES)   // 81920
#define GT 128                        // gemm threads

__device__ __forceinline__ void issue_stage(
    uint32_t sb, int stage,
    const __nv_bfloat16* Ah, const __nv_bfloat16* Al,
    const __nv_bfloat16* Bh, const __nv_bfloat16* Bl,
    int m0, int n0, int kc, int K, int tid)
{
    uint32_t sbase = sb + stage * STAGE_BYTES;
    #pragma unroll
    for (int i = 0; i < 16; i++) {
        int id = (i << 7) + tid;          // 0..2047
        int tile = id >> 9;               // 0..3 : AH AL BH BL
        int r = (id >> 2) & 127;
        int c = id & 3;                   // 16B chunk within 64B row data
        const __nv_bfloat16* src =
            (tile == 0) ? Ah : (tile == 1) ? Al : (tile == 2) ? Bh : Bl;
        int rowg = ((tile < 2) ? m0 : n0) + r;
        const void* g = src + (size_t)rowg * K + kc + (c << 3);
        uint32_t s = sbase + tile * TILE_BYTES + r * (SROW * 2) + (c << 4);
        asm volatile("cp.async.cg.shared.global [%0], [%1], 16;\n"
                     :: "r"(s), "l"(g));
    }
}

__global__ __launch_bounds__(GT, 2)
void k_gemm_mma(const __nv_bfloat16* __restrict__ Ah, const __nv_bfloat16* __restrict__ Al,
                const __nv_bfloat16* __restrict__ Bh, const __nv_bfloat16* __restrict__ Bl,
                const float* __restrict__ bias, const float* __restrict__ res,
                float* __restrict__ C,
                __nv_bfloat16* __restrict__ Ch, __nv_bfloat16* __restrict__ Cl,
                int M, int N, int K, int relu)
{
    extern __shared__ __align__(128) char sm2[];
    uint32_t sb = smem_u32(sm2);
    int tid = threadIdx.x;
    int lane = tid & 31, wid = tid >> 5;
    int wm = (wid & 1) << 6;    // warp M offset (0/64)
    int wn = (wid >> 1) << 6;   // warp N offset (0/64)
    int m0 = blockIdx.y << 7, n0 = blockIdx.x << 7;

    float acc[4][8][4];
    #pragma unroll
    for (int i = 0; i < 4; i++)
        #pragma unroll
        for (int j = 0; j < 8; j++)
            #pragma unroll
            for (int k = 0; k < 4; k++) acc[i][j][k] = 0.f;

    issue_stage(sb, 0, Ah, Al, Bh, Bl, m0, n0, 0, K, tid);
    asm volatile("cp.async.commit_group;\n" ::: "memory");
    issue_stage(sb, 1, Ah, Al, Bh, Bl, m0, n0, BK, K, tid);
    asm volatile("cp.async.commit_group;\n" ::: "memory");

    // ldmatrix lane address components
    int a_row = ((lane >> 3) & 1) * 8 + (lane & 7);
    int a_k   = (lane >> 4) << 3;
    int b_row = ((lane >> 4) << 3) + (lane & 7);
    int b_k   = ((lane >> 3) & 1) << 3;

    int niter = K / BK;
    for (int it = 0; it < niter; it++) {
        asm volatile("cp.async.wait_group 1;\n" ::: "memory");
        __syncthreads();
        int stage = it & 1;
        uint32_t st = sb + stage * STAGE_BYTES;
        #pragma unroll
        for (int ks = 0; ks < 2; ks++) {
            uint32_t ra[4][4], rbh[4][4], rbl[4][4];
            // A-hi (4 m16 tiles)
            #pragma unroll
            for (int i = 0; i < 4; i++)
                ldsm4(ra[i], st + ((wm + i * 16 + a_row) * SROW + ks * 16 + a_k) * 2);
            // B-hi, B-lo (4 n16 tiles each)
            #pragma unroll
            for (int j2 = 0; j2 < 4; j2++) {
                uint32_t boff = ((wn + j2 * 16 + b_row) * SROW + ks * 16 + b_k) * 2;
                ldsm4(rbh[j2], st + 2 * TILE_BYTES + boff);
                ldsm4(rbl[j2], st + 3 * TILE_BYTES + boff);
            }
            // pass 0: Ah * Bh
            #pragma unroll
            for (int i = 0; i < 4; i++)
                #pragma unroll
                for (int j2 = 0; j2 < 4; j2++) {
                    mma16816(acc[i][j2 * 2 + 0], ra[i], &rbh[j2][0]);
                    mma16816(acc[i][j2 * 2 + 1], ra[i], &rbh[j2][2]);
                }
            // pass 1: Ah * Bl
            #pragma unroll
            for (int i = 0; i < 4; i++)
                #pragma unroll
                for (int j2 = 0; j2 < 4; j2++) {
                    mma16816(acc[i][j2 * 2 + 0], ra[i], &rbl[j2][0]);
                    mma16816(acc[i][j2 * 2 + 1], ra[i], &rbl[j2][2]);
                }
            // A-lo (reuse ra regs)
            #pragma unroll
            for (int i = 0; i < 4; i++)
                ldsm4(ra[i], st + TILE_BYTES +
                      ((wm + i * 16 + a_row) * SROW + ks * 16 + a_k) * 2);
            // pass 2: Al * Bh
            #pragma unroll
            for (int i = 0; i < 4; i++)
                #pragma unroll
                for (int j2 = 0; j2 < 4; j2++) {
                    mma16816(acc[i][j2 * 2 + 0], ra[i], &rbh[j2][0]);
                    mma16816(acc[i][j2 * 2 + 1], ra[i], &rbh[j2][2]);
                }
        }
        __syncthreads();
        if (it + 2 < niter)
            issue_stage(sb, stage, Ah, Al, Bh, Bl, m0, n0, (it + 2) * BK, K, tid);
        asm volatile("cp.async.commit_group;\n" ::: "memory");
    }

    // Epilogue: thread (g,tg) holds rows g,g+8, cols 2*tg..+1 of each m16n8 tile
    int g = lane >> 2, tg = (lane & 3) << 1;
    #pragma unroll
    for (int i = 0; i < 4; i++) {
        int r0 = m0 + wm + i * 16 + g;
        #pragma unroll
        for (int j = 0; j < 8; j++) {
            int col = n0 + wn + j * 8 + tg;
            float v00 = acc[i][j][0], v01 = acc[i][j][1];
            float v10 = acc[i][j][2], v11 = acc[i][j][3];
            if (bias) {
                float2 bb = *(const float2*)(bias + col);
                v00 += bb.x; v01 += bb.y; v10 += bb.x; v11 += bb.y;
            }
            if (relu) {
                v00 = fmaxf(v00, 0.f); v01 = fmaxf(v01, 0.f);
                v10 = fmaxf(v10, 0.f); v11 = fmaxf(v11, 0.f);
            }
            size_t o0 = (size_t)r0 * N + col;
            size_t o1 = o0 + (size_t)8 * N;
            if (Ch) {
                __nv_bfloat16 h0, l0, h1, l1;
                split_bf16(v00, h0, l0); split_bf16(v01, h1, l1);
                *(__nv_bfloat162*)(Ch + o0) = __halves2bfloat162(h0, h1);
                *(__nv_bfloat162*)(Cl + o0) = __halves2bfloat162(l0, l1);
                split_bf16(v10, h0, l0); split_bf16(v11, h1, l1);
                *(__nv_bfloat162*)(Ch + o1) = __halves2bfloat162(h0, h1);
                *(__nv_bfloat162*)(Cl + o1) = __halves2bfloat162(l0, l1);
            } else {
                if (res) {
                    float2 r0v = *(const float2*)(res + o0);
                    float2 r1v = *(const float2*)(res + o1);
                    v00 += r0v.x; v01 += r0v.y; v10 += r1v.x; v11 += r1v.y;
                }
                *(float2*)(C + o0) = make_float2(v00, v01);
                *(float2*)(C + o1) = make_float2(v10, v11);
            }
        }
    }
}

// ---------------------------------------------------------------------------
// Causal attention, flash-style (fp32 SIMT). Block = (b, h, 64-query tile).
// Reads packed qkv [M][3072]; writes bf16 hi/lo split output [M][1024].
// ---------------------------------------------------------------------------
#define ATT_SMEM ((4 * 64 * 68 + 192) * 4)

__global__ __launch_bounds__(256)
void k_attn(const float* __restrict__ QKV,
            __nv_bfloat16* __restrict__ Oh, __nv_bfloat16* __restrict__ Ol)
{
    extern __shared__ __align__(16) float smA[];
    float* QsT  = smA;
    float* KsT  = smA + 64 * 68;
    float* Vs   = smA + 2 * 64 * 68;
    float* Ss   = smA + 3 * 64 * 68;
    float* mRow = smA + 4 * 64 * 68;
    float* sRow = mRow + 64;
    float* fRow = sRow + 64;

    int qt = blockIdx.x;
    int bh = blockIdx.y;
    int b = bh >> 4, h = bh & 15;
    int tid = threadIdx.x;
    int tx = tid & 15, ty = tid >> 4;
    size_t rbase = (size_t)b * Tm;     // row base
    const float* Q  = QKV + h * HSm;
    const float* Kx = QKV + 1024 + h * HSm;
    const float* Vx = QKV + 2048 + h * HSm;

    for (int i = tid; i < 1024; i += 256) {
        int r = i >> 4, c = (i & 15) << 2;
        float4 qv = *(const float4*)(Q + (rbase + qt * 64 + r) * QKVN + c);
        QsT[(c + 0) * 68 + r] = qv.x * 0.125f;
        QsT[(c + 1) * 68 + r] = qv.y * 0.125f;
        QsT[(c + 2) * 68 + r] = qv.z * 0.125f;
        QsT[(c + 3) * 68 + r] = qv.w * 0.125f;
    }
    if (tid < 64) { mRow[tid] = -1e30f; sRow[tid] = 0.f; }

    float acc[4][4] = {};

    for (int kt = 0; kt <= qt; kt++) {
        __syncthreads();
        for (int i = tid; i < 1024; i += 256) {
            int r = i >> 4, c = (i & 15) << 2;
            float4 kv = *(const float4*)(Kx + (rbase + kt * 64 + r) * QKVN + c);
            KsT[(c + 0) * 68 + r] = kv.x;
            KsT[(c + 1) * 68 + r] = kv.y;
            KsT[(c + 2) * 68 + r] = kv.z;
            KsT[(c + 3) * 68 + r] = kv.w;
            float4 vv = *(const float4*)(Vx + (rbase + kt * 64 + r) * QKVN + c);
            *(float4*)&Vs[r * 68 + c] = vv;
        }
        __syncthreads();

        float sc[4][4] = {};
        #pragma unroll 8
        for (int e = 0; e < 64; e++) {
            float4 qv = *(const float4*)&QsT[e * 68 + (ty << 2)];
            float4 kv = *(const float4*)&KsT[e * 68 + (tx << 2)];
            sc[0][0] += qv.x * kv.x; sc[0][1] += qv.x * kv.y;
            sc[0][2] += qv.x * kv.z; sc[0][3] += qv.x * kv.w;
            sc[1][0] += qv.y * kv.x; sc[1][1] += qv.y * kv.y;
            sc[1][2] += qv.y * kv.z; sc[1][3] += qv.y * kv.w;
            sc[2][0] += qv.z * kv.x; sc[2][1] += qv.z * kv.y;
            sc[2][2] += qv.z * kv.z; sc[2][3] += qv.z * kv.w;
            sc[3][0] += qv.w * kv.x; sc[3][1] += qv.w * kv.y;
            sc[3][2] += qv.w * kv.z; sc[3][3] += qv.w * kv.w;
        }
        #pragma unroll
        for (int i = 0; i < 4; i++)
            *(float4*)&Ss[((ty << 2) + i) * 68 + (tx << 2)] =
                make_float4(sc[i][0], sc[i][1], sc[i][2], sc[i][3]);
        __syncthreads();

        if (tid < 64) {
            int r = tid;
            int lim = (kt == qt) ? r : 63;
            float mOld = mRow[r];
            float mx = mOld;
            for (int j = 0; j <= lim; j++) mx = fmaxf(mx, Ss[r * 68 + j]);
            float f = __expf(mOld - mx);
            float sum = sRow[r] * f;
            for (int j = 0; j < 64; j++) {
                float p = (j <= lim) ? __expf(Ss[r * 68 + j] - mx) : 0.f;
                Ss[r * 68 + j] = p;
                sum += p;
            }
            mRow[r] = mx; sRow[r] = sum; fRow[r] = f;
        }
        __syncthreads();

        float f0 = fRow[(ty << 2) + 0], f1 = fRow[(ty << 2) + 1];
        float f2 = fRow[(ty << 2) + 2], f3 = fRow[(ty << 2) + 3];
        #pragma unroll
        for (int j = 0; j < 4; j++) {
            acc[0][j] *= f0; acc[1][j] *= f1; acc[2][j] *= f2; acc[3][j] *= f3;
        }
        #pragma unroll 8
        for (int j = 0; j < 64; j++) {
            float4 vv = *(const float4*)&Vs[j * 68 + (tx << 2)];
            float p0 = Ss[((ty << 2) + 0) * 68 + j];
            float p1 = Ss[((ty << 2) + 1) * 68 + j];
            float p2 = Ss[((ty << 2) + 2) * 68 + j];
            float p3 = Ss[((ty << 2) + 3) * 68 + j];
            acc[0][0] += p0 * vv.x; acc[0][1] += p0 * vv.y;
            acc[0][2] += p0 * vv.z; acc[0][3] += p0 * vv.w;
            acc[1][0] += p1 * vv.x; acc[1][1] += p1 * vv.y;
            acc[1][2] += p1 * vv.z; acc[1][3] += p1 * vv.w;
            acc[2][0] += p2 * vv.x; acc[2][1] += p2 * vv.y;
            acc[2][2] += p2 * vv.z; acc[2][3] += p2 * vv.w;
            acc[3][0] += p3 * vv.x; acc[3][1] += p3 * vv.y;
            acc[3][2] += p3 * vv.z; acc[3][3] += p3 * vv.w;
        }
    }

    #pragma unroll
    for (int i = 0; i < 4; i++) {
        float inv = 1.0f / sRow[(ty << 2) + i];
        size_t off = (rbase + qt * 64 + (ty << 2) + i) * Dm + h * HSm + (tx << 2);
        float v0 = acc[i][0] * inv, v1 = acc[i][1] * inv;
        float v2 = acc[i][2] * inv, v3 = acc[i][3] * inv;
        __nv_bfloat16 h0, l0, h1, l1, h2, l2, h3, l3;
        split_bf16(v0, h0, l0); split_bf16(v1, h1, l1);
        split_bf16(v2, h2, l2); split_bf16(v3, h3, l3);
        *(__nv_bfloat162*)(Oh + off)     = __halves2bfloat162(h0, h1);
        *(__nv_bfloat162*)(Oh + off + 2) = __halves2bfloat162(h2, h3);
        *(__nv_bfloat162*)(Ol + off)     = __halves2bfloat162(l0, l1);
        *(__nv_bfloat162*)(Ol + off + 2) = __halves2bfloat162(l2, l3);
    }
}

// ---------------------------------------------------------------------------
// Host orchestration (graph-capturable: kernel launches only)
// ---------------------------------------------------------------------------
extern "C" void kernel_launch(void* const* d_in, const int* in_sizes, int n_in,
                              void* d_out, int out_size)
{
    (void)in_sizes; (void)n_in; (void)out_size;
    const int*   x      = (const int*)  d_in[0];
    const float* tok    = (const float*)d_in[1];
    const float* pos    = (const float*)d_in[2];
    const float* wq     = (const float*)d_in[3];
    const float* wk     = (const float*)d_in[4];
    const float* wv     = (const float*)d_in[5];
    const float* w_o    = (const float*)d_in[6];
    const float* b_o    = (const float*)d_in[7];
    const float* ln1_g  = (const float*)d_in[8];
    const float* ln1_b  = (const float*)d_in[9];
    const float* ln2_g  = (const float*)d_in[10];
    const float* ln2_b  = (const float*)d_in[11];
    const float* w1     = (const float*)d_in[12];
    const float* b1     = (const float*)d_in[13];
    const float* w2     = (const float*)d_in[14];
    const float* b2     = (const float*)d_in[15];
    const float* lnf_g  = (const float*)d_in[16];
    const float* lnf_b  = (const float*)d_in[17];
    const float* w_lm   = (const float*)d_in[18];
    const float* b_lm   = (const float*)d_in[19];
    float* out = (float*)d_out;

    float *hb, *hn, *qkvb;
    cudaGetSymbolAddress((void**)&hb, g_h);
    cudaGetSymbolAddress((void**)&hn, g_hn);
    cudaGetSymbolAddress((void**)&qkvb, g_qkv);

    __nv_bfloat16 *ah,*al,*fh,*fl,*wqkvh,*wqkvl,*oh,*ol,*w1h,*w1l,*w2h,*w2l,*lh,*ll;
    cudaGetSymbolAddress((void**)&ah, g_ah);       cudaGetSymbolAddress((void**)&al, g_al);
    cudaGetSymbolAddress((void**)&fh, g_fh);       cudaGetSymbolAddress((void**)&fl, g_fl);
    cudaGetSymbolAddress((void**)&wqkvh, g_wqkvh); cudaGetSymbolAddress((void**)&wqkvl, g_wqkvl);
    cudaGetSymbolAddress((void**)&oh, g_oh);       cudaGetSymbolAddress((void**)&ol, g_ol);
    cudaGetSymbolAddress((void**)&w1h, g_1h);      cudaGetSymbolAddress((void**)&w1l, g_1l);
    cudaGetSymbolAddress((void**)&w2h, g_2h);      cudaGetSymbolAddress((void**)&w2l, g_2l);
    cudaGetSymbolAddress((void**)&lh, g_lh);       cudaGetSymbolAddress((void**)&ll, g_ll);

    cudaFuncSetAttribute(k_attn, cudaFuncAttributeMaxDynamicSharedMemorySize, ATT_SMEM);
    cudaFuncSetAttribute(k_gemm_mma, cudaFuncAttributeMaxDynamicSharedMemorySize, GEMM_SMEM);

    dim3 g1(Dm / 128, Mrows / 128);     // N=1024
    dim3 gq(QKVN / 128, Mrows / 128);   // N=3072
    dim3 g2(FFm / 128, Mrows / 128);    // N=4096
    dim3 gl(Vm / 128, Mrows / 128);     // N=8192
    dim3 ga(Tm / 64, Bm_ * Hm);

    k_embed<<<Mrows, 256>>>(x, tok, pos, hb);

    for (int l = 0; l < Lm; l++) {
        size_t wofs = (size_t)l * Hm * Dm * HSm;
        k_ln<<<Mrows, 256>>>(hb, ln1_g + l * Dm, ln1_b + l * Dm, hn, ah, al);
        k_conv_qkv<<<dim3(16, 16, 3), 256>>>(wq + wofs, wk + wofs, wv + wofs,
                                             wqkvh, wqkvl);
        k_gemm_mma<<<gq, GT, GEMM_SMEM>>>(ah, al, wqkvh, wqkvl, nullptr, nullptr,
                                          qkvb, nullptr, nullptr,
                                          Mrows, QKVN, Dm, 0);
        k_attn<<<ga, 256, ATT_SMEM>>>(qkvb, ah, al);

        k_conv_t<<<dim3(16, 16), 256>>>(w_o + (size_t)l * Dm * Dm, oh, ol, Dm, Dm);
        // h = hn + att @ w_o + b_o
        k_gemm_mma<<<g1, GT, GEMM_SMEM>>>(ah, al, oh, ol, b_o + l * Dm, hn, hb,
                                          nullptr, nullptr, Mrows, Dm, Dm, 0);
        k_ln<<<Mrows, 256>>>(hb, ln2_g + l * Dm, ln2_b + l * Dm, hn, ah, al);

        k_conv_t<<<dim3(64, 16), 256>>>(w1 + (size_t)l * Dm * FFm, w1h, w1l, Dm, FFm);
        // ffn1 = relu(hn @ w1 + b1)  -> split bf16 output directly
        k_gemm_mma<<<g2, GT, GEMM_SMEM>>>(ah, al, w1h, w1l, b1 + l * FFm, nullptr,
                                          nullptr, fh, fl, Mrows, FFm, Dm, 1);
        k_conv_t<<<dim3(16, 64), 256>>>(w2 + (size_t)l * FFm * Dm, w2h, w2l, FFm, Dm);
        // h = hn + ffn1 @ w2 + b2
        k_gemm_mma<<<g1, GT, GEMM_SMEM>>>(fh, fl, w2h, w2l, b2 + l * Dm, hn, hb,
                                          nullptr, nullptr, Mrows, Dm, FFm, 0);
    }

    k_ln<<<Mrows, 256>>>(hb, lnf_g, lnf_b, hn, ah, al);
    k_conv_t<<<dim3(128, 16), 256>>>(w_lm, lh, ll, Dm, Vm);
    k_gemm_mma<<<gl, GT, GEMM_SMEM>>>(ah, al, lh, ll, b_lm, nullptr, out,
                                      nullptr, nullptr, Mrows, Vm, Dm, 0);
}